// round 7
// baseline (speedup 1.0000x reference)
#include <cuda_runtime.h>
#include <cuda_fp16.h>
#include <cstdint>
#include <cstddef>

#define BB  8192
#define TT  8
#define PPD 256
#define GGD 512
#define CCH 768
#define H0  512
#define H1  256

// ------------------------- device scratch (352 MB total) -------------------
__device__ __align__(256) __half g_comb_h [(size_t)BB*CCH];
__device__ __align__(256) __half g_comb_l [(size_t)BB*CCH];
__device__ __align__(256) __half g_pers_h [(size_t)BB*GGD];
__device__ __align__(256) __half g_pers_l [(size_t)BB*GGD];
__device__ __align__(256) __half g_wppn0_h[(size_t)TT*H0*CCH];
__device__ __align__(256) __half g_wppn0_l[(size_t)TT*H0*CCH];
__device__ __align__(256) __half g_wgt0_h [(size_t)TT*H0*H0];
__device__ __align__(256) __half g_wgt0_l [(size_t)TT*H0*H0];
__device__ __align__(256) __half g_wtw0_h [(size_t)TT*H0*GGD];
__device__ __align__(256) __half g_wtw0_l [(size_t)TT*H0*GGD];
__device__ __align__(256) __half g_wppn1_h[(size_t)TT*H1*CCH];
__device__ __align__(256) __half g_wppn1_l[(size_t)TT*H1*CCH];
__device__ __align__(256) __half g_wgt1_h [(size_t)TT*H1*H1];
__device__ __align__(256) __half g_wgt1_l [(size_t)TT*H1*H1];
__device__ __align__(256) __half g_wtw1_h [(size_t)TT*H1*H0];
__device__ __align__(256) __half g_wtw1_l [(size_t)TT*H1*H0];

// Aliased activation pools (see R5/R6: stream order makes every overwrite safe)
#define P64  67108864ull
#define P32  33554432ull
__device__ __align__(256) unsigned char g_poolA[2ull*P64];
__device__ __align__(256) unsigned char g_poolB[2ull*P64];

enum { HP_COMB=0, HP_PERS, HP_WPPN0, HP_WGT0, HP_WTW0, HP_WPPN1, HP_WGT1, HP_WTW1,
       HP_H0, HP_X0, HP_G0, HP_H1, HP_G1, HP_X1 };

__device__ __forceinline__ __half* get_hbuf(int id, int plane){
    switch(id){
        case HP_COMB:  return plane ? g_comb_l  : g_comb_h;
        case HP_PERS:  return plane ? g_pers_l  : g_pers_h;
        case HP_WPPN0: return plane ? g_wppn0_l : g_wppn0_h;
        case HP_WGT0:  return plane ? g_wgt0_l  : g_wgt0_h;
        case HP_WTW0:  return plane ? g_wtw0_l  : g_wtw0_h;
        case HP_WPPN1: return plane ? g_wppn1_l : g_wppn1_h;
        case HP_WGT1:  return plane ? g_wgt1_l  : g_wgt1_h;
        case HP_WTW1:  return plane ? g_wtw1_l  : g_wtw1_h;
        case HP_H0:    return (__half*)(g_poolA + (plane ? P64 : 0));
        case HP_X0:    return (__half*)(g_poolA + (plane ? P64 : 0));
        case HP_G0:    return (__half*)(g_poolB + (plane ? P64 : 0));
        case HP_H1:    return (__half*)(g_poolB + (plane ? P32 : 0));
        case HP_G1:    return (__half*)(g_poolB + P64 + (plane ? P32 : 0));
        default:       return (__half*)(g_poolB + (plane ? P32 : 0));   // HP_X1
    }
}

// ------------------------- small helpers ----------------------------------
__device__ __forceinline__ uint32_t smem_u32(const void* p){
    uint32_t a;
    asm("{ .reg .u64 t; cvta.to.shared.u64 t, %1; cvt.u32.u64 %0, t; }" : "=r"(a) : "l"(p));
    return a;
}
__device__ __forceinline__ void split_f32(float v, __half& hi, __half& lo){
    hi = __float2half_rn(v);
    lo = __float2half_rn(v - __half2float(hi));
}
__device__ __forceinline__ void cp16(uint32_t dst, const void* src){
    asm volatile("cp.async.cg.shared.global [%0], [%1], 16;" :: "r"(dst), "l"(src));
}
#define CP_COMMIT() asm volatile("cp.async.commit_group;" ::: "memory")
#define LDSM_X4(r0,r1,r2,r3,addr) \
    asm volatile("ldmatrix.sync.aligned.m8n8.x4.shared.b16 {%0,%1,%2,%3}, [%4];" \
        : "=r"(r0), "=r"(r1), "=r"(r2), "=r"(r3) : "r"(addr))
#define MMA16816(d, a0, a1, a2, a3, b0, b1) \
    asm volatile("mma.sync.aligned.m16n8k16.row.col.f32.f16.f16.f32 " \
        "{%0,%1,%2,%3}, {%4,%5,%6,%7}, {%8,%9}, {%0,%1,%2,%3};" \
        : "+f"((d)[0]), "+f"((d)[1]), "+f"((d)[2]), "+f"((d)[3]) \
        : "r"(a0), "r"(a1), "r"(a2), "r"(a3), "r"(b0), "r"(b1))

// ------------------------- prep kernels -----------------------------------
__global__ void concat_convert_k(const float* __restrict__ prior, const float* __restrict__ gen){
    int i = blockIdx.x * blockDim.x + threadIdx.x;
    if (i >= BB * CCH) return;
    int b = i / CCH, c = i % CCH;
    float v = (c < PPD) ? prior[(size_t)b * PPD + c] : gen[(size_t)b * GGD + (c - PPD)];
    __half hi, lo; split_f32(v, hi, lo);
    g_comb_h[i] = hi; g_comb_l[i] = lo;
}
__global__ void pers_convert_k(const float* __restrict__ pers){
    int i = blockIdx.x * blockDim.x + threadIdx.x;
    if (i >= BB * GGD) return;
    __half hi, lo; split_f32(pers[i], hi, lo);
    g_pers_h[i] = hi; g_pers_l[i] = lo;
}
__global__ void transpose_convert_k(const float* __restrict__ W, int out_id, int Kd, int Nd){
    __shared__ float tile[32][33];
    int t  = blockIdx.z;
    int k0 = blockIdx.x * 32, n0 = blockIdx.y * 32;
    const float* src = W + (size_t)t * Kd * Nd;
    __half* dh = get_hbuf(out_id, 0) + (size_t)t * Nd * Kd;
    __half* dl = get_hbuf(out_id, 1) + (size_t)t * Nd * Kd;
    int x = threadIdx.x;
    for (int yy = threadIdx.y; yy < 32; yy += 8)
        tile[yy][x] = src[(size_t)(k0 + yy) * Nd + n0 + x];
    __syncthreads();
    for (int yy = threadIdx.y; yy < 32; yy += 8){
        float v = tile[x][yy];
        __half hi, lo; split_f32(v, hi, lo);
        size_t o = (size_t)(n0 + yy) * Kd + k0 + x;
        dh[o] = hi; dl[o] = lo;
    }
}

// ------------------------- fp16-split GEMM --------------------------------
// CTA 128x128, 8 warps (4M x 2N), warp tile 32x64. KC=32, 3-stage cp.async.
// D = A_hi*B_hi + A_hi*B_lo + A_lo*B_hi  (fp32 accumulate), term-major MMA order.
#define ROWB 80
#define TILEB 10240
#define STG   40960
#define NSTAGE 3
#define SMEM_DYN (NSTAGE*STG)

__global__ void __launch_bounds__(256, 1) gemm_fp16s(
    int a_id, size_t a_tstr, int lda, int K,
    int b_id, const float* __restrict__ bias,
    int aux_id, int out_id, int Ntot, int epi)
{
    extern __shared__ char smem[];
    uint32_t sb = smem_u32(smem);
    int tid = threadIdx.x, wid = tid >> 5, lid = tid & 31;
    int warp_m = wid & 3, warp_n = wid >> 2;
    int t  = blockIdx.z;
    int m0 = blockIdx.x * 128;
    int n0 = blockIdx.y * 128;

    const __half* Ah = get_hbuf(a_id, 0) + (size_t)t * a_tstr + (size_t)m0 * lda;
    const __half* Al = get_hbuf(a_id, 1) + (size_t)t * a_tstr + (size_t)m0 * lda;
    const __half* Bh = get_hbuf(b_id, 0) + ((size_t)t * Ntot + n0) * K;
    const __half* Bl = get_hbuf(b_id, 1) + ((size_t)t * Ntot + n0) * K;

    float acc[2][8][4];
    #pragma unroll
    for (int mi = 0; mi < 2; mi++)
        #pragma unroll
        for (int ni = 0; ni < 8; ni++)
            #pragma unroll
            for (int j = 0; j < 4; j++) acc[mi][ni][j] = 0.f;

    int nk = K >> 5;

    int lq = lid >> 3, lr = lid & 7;
    uint32_t a_row_base = (uint32_t)(warp_m * 32 + ((lq & 1) << 3) + lr);
    uint32_t a_colb     = (uint32_t)((lq >> 1) << 4);
    uint32_t b_row_base = (uint32_t)(warp_n * 64 + ((lq >> 1) << 3) + lr);
    uint32_t b_colb     = (uint32_t)((lq & 1) << 4);

    // per-thread loader slot (hoisted)
    int l_tile = tid >> 6;            // 0..3 : Ah, Al, Bh, Bl  (64 threads each)
    int l_rem  = tid & 63;
    // each of 64 threads covers 2 rows x 4 cols? No: tile = 128 rows x 4 cols(16B);
    // 512 slots per tile, 64 threads -> 8 slots each (stride 64).
    const __half* l_src0 = (l_tile == 0) ? Ah : (l_tile == 1) ? Al : (l_tile == 2) ? Bh : Bl;
    int l_ld = (l_tile < 2) ? lda : K;
    uint32_t l_dstbase = sb + (uint32_t)l_tile * TILEB;

    auto load_chunk = [&](int kc, int stage_sel){
        uint32_t stage = (uint32_t)stage_sel * (uint32_t)STG;
        const __half* src = l_src0 + kc * 32;
        #pragma unroll
        for (int it = 0; it < 8; it++){
            int slot = it * 64 + l_rem;
            int row  = slot >> 2, c = slot & 3;
            cp16(l_dstbase + stage + (uint32_t)row * ROWB + (uint32_t)c * 16,
                 src + (size_t)row * l_ld + c * 8);
        }
        CP_COMMIT();
    };

    load_chunk(0, 0);
    if (nk > 1) load_chunk(1, 1);

    int stage = 0;
    for (int kc = 0; kc < nk; kc++){
        if (kc + 1 < nk)
            asm volatile("cp.async.wait_group 1;" ::: "memory");
        else
            asm volatile("cp.async.wait_group 0;" ::: "memory");
        __syncthreads();

        uint32_t stg_b = sb + (uint32_t)stage * STG;
        uint32_t sAh = stg_b;
        uint32_t sAl = stg_b + TILEB;
        uint32_t sBh = stg_b + 2 * TILEB;
        uint32_t sBl = stg_b + 3 * TILEB;

        #pragma unroll
        for (int s = 0; s < 2; s++){
            uint32_t scol = (uint32_t)(s * 32);
            uint32_t ah[2][4], al[2][4];
            #pragma unroll
            for (int mi = 0; mi < 2; mi++){
                uint32_t aoff = (a_row_base + (uint32_t)(mi * 16)) * ROWB + scol + a_colb;
                LDSM_X4(ah[mi][0], ah[mi][1], ah[mi][2], ah[mi][3], sAh + aoff);
                LDSM_X4(al[mi][0], al[mi][1], al[mi][2], al[mi][3], sAl + aoff);
            }
            uint32_t bh[4][4], bl[4][4];
            #pragma unroll
            for (int p = 0; p < 4; p++){
                uint32_t boff = (b_row_base + (uint32_t)(p * 16)) * ROWB + scol + b_colb;
                LDSM_X4(bh[p][0], bh[p][1], bh[p][2], bh[p][3], sBh + boff);
                LDSM_X4(bl[p][0], bl[p][1], bl[p][2], bl[p][3], sBl + boff);
            }
            // term-major: 16 independent MMAs between accumulator reuses
            #pragma unroll
            for (int p = 0; p < 4; p++)
                #pragma unroll
                for (int mi = 0; mi < 2; mi++){
                    MMA16816(acc[mi][2*p],   ah[mi][0], ah[mi][1], ah[mi][2], ah[mi][3], bh[p][0], bh[p][1]);
                    MMA16816(acc[mi][2*p+1], ah[mi][0], ah[mi][1], ah[mi][2], ah[mi][3], bh[p][2], bh[p][3]);
                }
            #pragma unroll
            for (int p = 0; p < 4; p++)
                #pragma unroll
                for (int mi = 0; mi < 2; mi++){
                    MMA16816(acc[mi][2*p],   ah[mi][0], ah[mi][1], ah[mi][2], ah[mi][3], bl[p][0], bl[p][1]);
                    MMA16816(acc[mi][2*p+1], ah[mi][0], ah[mi][1], ah[mi][2], ah[mi][3], bl[p][2], bl[p][3]);
                }
            #pragma unroll
            for (int p = 0; p < 4; p++)
                #pragma unroll
                for (int mi = 0; mi < 2; mi++){
                    MMA16816(acc[mi][2*p],   al[mi][0], al[mi][1], al[mi][2], al[mi][3], bh[p][0], bh[p][1]);
                    MMA16816(acc[mi][2*p+1], al[mi][0], al[mi][1], al[mi][2], al[mi][3], bh[p][2], bh[p][3]);
                }
        }
        __syncthreads();
        if (kc + 2 < nk)
            load_chunk(kc + 2, (stage + 2 >= NSTAGE) ? (stage + 2 - NSTAGE) : (stage + 2));
        stage = (stage + 1 >= NSTAGE) ? 0 : (stage + 1);
    }

    // ---------------- epilogue ----------------
    const float* biasp = bias + (size_t)t * Ntot;
    const __half* axh = nullptr; const __half* axl = nullptr;
    if (epi){
        axh = get_hbuf(aux_id, 0) + (size_t)t * BB * Ntot;
        axl = get_hbuf(aux_id, 1) + (size_t)t * BB * Ntot;
    }
    __half* oh = get_hbuf(out_id, 0) + (size_t)t * BB * Ntot;
    __half* ol = get_hbuf(out_id, 1) + (size_t)t * BB * Ntot;

    int g = lid >> 2, tig = lid & 3;
    #pragma unroll
    for (int mi = 0; mi < 2; mi++){
        #pragma unroll
        for (int ni = 0; ni < 8; ni++){
            int col = n0 + warp_n * 64 + ni * 8 + 2 * tig;
            float2 bv = *(const float2*)(biasp + col);
            int row0 = m0 + warp_m * 32 + mi * 16 + g;
            #pragma unroll
            for (int h = 0; h < 2; h++){
                int row = row0 + h * 8;
                size_t off = (size_t)row * Ntot + col;
                float v0 = acc[mi][ni][2*h]   + bv.x;
                float v1 = acc[mi][ni][2*h+1] + bv.y;
                float a0 = 0.f, a1 = 0.f;
                if (epi){
                    __half2 hv = *(const __half2*)(axh + off);
                    __half2 lv = *(const __half2*)(axl + off);
                    a0 = __half2float(hv.x) + __half2float(lv.x);
                    a1 = __half2float(hv.y) + __half2float(lv.y);
                }
                float r0, r1;
                if (epi == 0){
                    r0 = fmaxf(v0, 0.f); r1 = fmaxf(v1, 0.f);
                } else if (epi == 1){
                    r0 = a0 * (1.f / (1.f + __expf(-2.f * v0)));
                    r1 = a1 * (1.f / (1.f + __expf(-2.f * v1)));
                } else {
                    r0 = fmaxf(v0 * a0, 0.f); r1 = fmaxf(v1 * a1, 0.f);
                }
                __half h0v, l0v, h1v, l1v;
                split_f32(r0, h0v, l0v); split_f32(r1, h1v, l1v);
                *(__half2*)(oh + off) = __halves2half2(h0v, h1v);
                *(__half2*)(ol + off) = __halves2half2(l0v, l1v);
            }
        }
    }
}

// ------------------------- output layer -----------------------------------
__global__ void out_k(const float* __restrict__ W2, const float* __restrict__ b2,
                      float* __restrict__ out){
    int b = blockIdx.x;
    int wid = threadIdx.x >> 5, lid = threadIdx.x & 31;   // wid = task
    const __half* xh = get_hbuf(HP_X1, 0) + ((size_t)wid * BB + b) * H1;
    const __half* xl = get_hbuf(HP_X1, 1) + ((size_t)wid * BB + b) * H1;
    const float* wr = W2 + (size_t)wid * H1;
    float s = 0.f;
    #pragma unroll
    for (int j = 0; j < 8; j++){
        int i = lid + 32 * j;
        s += (__half2float(xh[i]) + __half2float(xl[i])) * wr[i];
    }
    #pragma unroll
    for (int o = 16; o > 0; o >>= 1)
        s += __shfl_down_sync(0xFFFFFFFFu, s, o);
    if (lid == 0) out[(size_t)b * TT + wid] = s + b2[wid];
}

// ------------------------- launch -----------------------------------------
extern "C" void kernel_launch(void* const* d_in, const int* in_sizes, int n_in,
                              void* d_out, int out_size) {
    const float* prior    = (const float*)d_in[0];
    const float* gen      = (const float*)d_in[1];
    const float* pers     = (const float*)d_in[2];
    const float* tower_W0 = (const float*)d_in[3];
    const float* tower_b0 = (const float*)d_in[4];
    const float* tower_W1 = (const float*)d_in[5];
    const float* tower_b1 = (const float*)d_in[6];
    const float* tower_W2 = (const float*)d_in[7];
    const float* tower_b2 = (const float*)d_in[8];
    const float* ppn0_W   = (const float*)d_in[9];
    const float* ppn0_b   = (const float*)d_in[10];
    const float* gate0_W  = (const float*)d_in[11];
    const float* gate0_b  = (const float*)d_in[12];
    const float* ppn1_W   = (const float*)d_in[13];
    const float* ppn1_b   = (const float*)d_in[14];
    const float* gate1_W  = (const float*)d_in[15];
    const float* gate1_b  = (const float*)d_in[16];

    cudaFuncSetAttribute(gemm_fp16s,
                         cudaFuncAttributeMaxDynamicSharedMemorySize, SMEM_DYN);

    concat_convert_k<<<(BB * CCH) / 256, 256>>>(prior, gen);
    pers_convert_k<<<(BB * GGD) / 256, 256>>>(pers);

    dim3 tb(32, 8);
    transpose_convert_k<<<dim3(CCH/32, H0/32, TT), tb>>>(ppn0_W,   HP_WPPN0, CCH, H0);
    transpose_convert_k<<<dim3(H0/32,  H0/32, TT), tb>>>(gate0_W,  HP_WGT0,  H0,  H0);
    transpose_convert_k<<<dim3(GGD/32, H0/32, TT), tb>>>(tower_W0, HP_WTW0,  GGD, H0);
    transpose_convert_k<<<dim3(CCH/32, H1/32, TT), tb>>>(ppn1_W,   HP_WPPN1, CCH, H1);
    transpose_convert_k<<<dim3(H1/32,  H1/32, TT), tb>>>(gate1_W,  HP_WGT1,  H1,  H1);
    transpose_convert_k<<<dim3(H0/32,  H1/32, TT), tb>>>(tower_W1, HP_WTW1,  H0,  H1);

    // ppn0: h0 = relu(comb @ W + b)                 [K=768, N=512]
    gemm_fp16s<<<dim3(BB/128, H0/128, TT), 256, SMEM_DYN>>>(
        HP_COMB, 0, CCH, CCH, HP_WPPN0, ppn0_b, 0, HP_H0, H0, 0);
    // gate0: g0 = h0 * sigmoid(2*(h0 @ Wg + b))     [K=512, N=512]
    gemm_fp16s<<<dim3(BB/128, H0/128, TT), 256, SMEM_DYN>>>(
        HP_H0, (size_t)BB*H0, H0, H0, HP_WGT0, gate0_b, HP_H0, HP_G0, H0, 1);
    // tower0: x0 = relu((pers @ W0 + b0) * g0)      [K=512, N=512]
    gemm_fp16s<<<dim3(BB/128, H0/128, TT), 256, SMEM_DYN>>>(
        HP_PERS, 0, GGD, GGD, HP_WTW0, tower_b0, HP_G0, HP_X0, H0, 2);
    // ppn1: h1 = relu(comb @ W + b)                 [K=768, N=256]
    gemm_fp16s<<<dim3(BB/128, H1/128, TT), 256, SMEM_DYN>>>(
        HP_COMB, 0, CCH, CCH, HP_WPPN1, ppn1_b, 0, HP_H1, H1, 0);
    // gate1: g1 = h1 * sigmoid(2*(h1 @ Wg + b))     [K=256, N=256]
    gemm_fp16s<<<dim3(BB/128, H1/128, TT), 256, SMEM_DYN>>>(
        HP_H1, (size_t)BB*H1, H1, H1, HP_WGT1, gate1_b, HP_H1, HP_G1, H1, 1);
    // tower1: x1 = relu((x0 @ W1 + b1) * g1)        [K=512, N=256]
    gemm_fp16s<<<dim3(BB/128, H1/128, TT), 256, SMEM_DYN>>>(
        HP_X0, (size_t)BB*H0, H0, H0, HP_WTW1, tower_b1, HP_G1, HP_X1, H1, 2);

    out_k<<<BB, 256>>>(tower_W2, tower_b2, (float*)d_out);
}

// round 8
// speedup vs baseline: 1.2967x; 1.2967x over previous
#include <cuda_runtime.h>
#include <cuda_fp16.h>
#include <cstdint>
#include <cstddef>

#define BB  8192
#define TT  8
#define PPD 256
#define GGD 512
#define CCH 768
#define H0  512
#define H1  256

// ------------------------- device scratch (352 MB total) -------------------
__device__ __align__(256) __half g_comb_h [(size_t)BB*CCH];
__device__ __align__(256) __half g_comb_l [(size_t)BB*CCH];
__device__ __align__(256) __half g_pers_h [(size_t)BB*GGD];
__device__ __align__(256) __half g_pers_l [(size_t)BB*GGD];
__device__ __align__(256) __half g_wppn0_h[(size_t)TT*H0*CCH];
__device__ __align__(256) __half g_wppn0_l[(size_t)TT*H0*CCH];
__device__ __align__(256) __half g_wgt0_h [(size_t)TT*H0*H0];
__device__ __align__(256) __half g_wgt0_l [(size_t)TT*H0*H0];
__device__ __align__(256) __half g_wtw0_h [(size_t)TT*H0*GGD];
__device__ __align__(256) __half g_wtw0_l [(size_t)TT*H0*GGD];
__device__ __align__(256) __half g_wppn1_h[(size_t)TT*H1*CCH];
__device__ __align__(256) __half g_wppn1_l[(size_t)TT*H1*CCH];
__device__ __align__(256) __half g_wgt1_h [(size_t)TT*H1*H1];
__device__ __align__(256) __half g_wgt1_l [(size_t)TT*H1*H1];
__device__ __align__(256) __half g_wtw1_h [(size_t)TT*H1*H0];
__device__ __align__(256) __half g_wtw1_l [(size_t)TT*H1*H0];

// Aliased activation pools (stream order makes every overwrite safe; see R5/R6)
#define P64  67108864ull
#define P32  33554432ull
__device__ __align__(256) unsigned char g_poolA[2ull*P64];
__device__ __align__(256) unsigned char g_poolB[2ull*P64];

enum { HP_COMB=0, HP_PERS, HP_WPPN0, HP_WGT0, HP_WTW0, HP_WPPN1, HP_WGT1, HP_WTW1,
       HP_H0, HP_X0, HP_G0, HP_H1, HP_G1, HP_X1 };

__device__ __forceinline__ __half* get_hbuf(int id, int plane){
    switch(id){
        case HP_COMB:  return plane ? g_comb_l  : g_comb_h;
        case HP_PERS:  return plane ? g_pers_l  : g_pers_h;
        case HP_WPPN0: return plane ? g_wppn0_l : g_wppn0_h;
        case HP_WGT0:  return plane ? g_wgt0_l  : g_wgt0_h;
        case HP_WTW0:  return plane ? g_wtw0_l  : g_wtw0_h;
        case HP_WPPN1: return plane ? g_wppn1_l : g_wppn1_h;
        case HP_WGT1:  return plane ? g_wgt1_l  : g_wgt1_h;
        case HP_WTW1:  return plane ? g_wtw1_l  : g_wtw1_h;
        case HP_H0:    return (__half*)(g_poolA + (plane ? P64 : 0));
        case HP_X0:    return (__half*)(g_poolA + (plane ? P64 : 0));
        case HP_G0:    return (__half*)(g_poolB + (plane ? P64 : 0));
        case HP_H1:    return (__half*)(g_poolB + (plane ? P32 : 0));
        case HP_G1:    return (__half*)(g_poolB + P64 + (plane ? P32 : 0));
        default:       return (__half*)(g_poolB + (plane ? P32 : 0));   // HP_X1
    }
}

// ------------------------- small helpers ----------------------------------
__device__ __forceinline__ uint32_t smem_u32(const void* p){
    uint32_t a;
    asm("{ .reg .u64 t; cvta.to.shared.u64 t, %1; cvt.u32.u64 %0, t; }" : "=r"(a) : "l"(p));
    return a;
}
__device__ __forceinline__ void split_f32(float v, __half& hi, __half& lo){
    hi = __float2half_rn(v);
    lo = __float2half_rn(v - __half2float(hi));
}
__device__ __forceinline__ void cp16(uint32_t dst, const void* src){
    asm volatile("cp.async.cg.shared.global [%0], [%1], 16;" :: "r"(dst), "l"(src));
}
#define CP_COMMIT() asm volatile("cp.async.commit_group;" ::: "memory")
#define LDSM_X4(r0,r1,r2,r3,addr) \
    asm volatile("ldmatrix.sync.aligned.m8n8.x4.shared.b16 {%0,%1,%2,%3}, [%4];" \
        : "=r"(r0), "=r"(r1), "=r"(r2), "=r"(r3) : "r"(addr))
#define MMA16816(d, a, b0, b1) \
    asm volatile("mma.sync.aligned.m16n8k16.row.col.f32.f16.f16.f32 " \
        "{%0,%1,%2,%3}, {%4,%5,%6,%7}, {%8,%9}, {%0,%1,%2,%3};" \
        : "+f"((d)[0]), "+f"((d)[1]), "+f"((d)[2]), "+f"((d)[3]) \
        : "r"((a)[0]), "r"((a)[1]), "r"((a)[2]), "r"((a)[3]), "r"(b0), "r"(b1))

// ------------------------- prep kernels -----------------------------------
__global__ void concat_convert_k(const float* __restrict__ prior, const float* __restrict__ gen){
    int i = blockIdx.x * blockDim.x + threadIdx.x;
    if (i >= BB * CCH) return;
    int b = i / CCH, c = i % CCH;
    float v = (c < PPD) ? prior[(size_t)b * PPD + c] : gen[(size_t)b * GGD + (c - PPD)];
    __half hi, lo; split_f32(v, hi, lo);
    g_comb_h[i] = hi; g_comb_l[i] = lo;
}
__global__ void pers_convert_k(const float* __restrict__ pers){
    int i = blockIdx.x * blockDim.x + threadIdx.x;
    if (i >= BB * GGD) return;
    __half hi, lo; split_f32(pers[i], hi, lo);
    g_pers_h[i] = hi; g_pers_l[i] = lo;
}

// One fused kernel transposes+converts ALL six weights.
// Tile table (per task): ppn0 384 | gate0 256 | tw0 256 | ppn1 192 | gate1 64 | tw1 128 = 1280
__global__ void transpose_all_k(const float* __restrict__ Wp0, const float* __restrict__ Wg0,
                                const float* __restrict__ Wt0, const float* __restrict__ Wp1,
                                const float* __restrict__ Wg1, const float* __restrict__ Wt1){
    __shared__ float tile[32][33];
    int t = blockIdx.z;
    int bid = blockIdx.x;
    const float* src; __half* dh; __half* dl; int Kd, Nd, idx;
    if      (bid < 384)  { src=Wp0; dh=g_wppn0_h; dl=g_wppn0_l; Kd=CCH; Nd=H0; idx=bid; }
    else if (bid < 640)  { src=Wg0; dh=g_wgt0_h;  dl=g_wgt0_l;  Kd=H0;  Nd=H0; idx=bid-384; }
    else if (bid < 896)  { src=Wt0; dh=g_wtw0_h;  dl=g_wtw0_l;  Kd=GGD; Nd=H0; idx=bid-640; }
    else if (bid < 1088) { src=Wp1; dh=g_wppn1_h; dl=g_wppn1_l; Kd=CCH; Nd=H1; idx=bid-896; }
    else if (bid < 1152) { src=Wg1; dh=g_wgt1_h;  dl=g_wgt1_l;  Kd=H1;  Nd=H1; idx=bid-1088; }
    else                 { src=Wt1; dh=g_wtw1_h;  dl=g_wtw1_l;  Kd=H0;  Nd=H1; idx=bid-1152; }
    int kt = Kd / 32;
    int k0 = (idx % kt) * 32, n0 = (idx / kt) * 32;
    src += (size_t)t * Kd * Nd;
    dh  += (size_t)t * Nd * Kd;
    dl  += (size_t)t * Nd * Kd;
    int x = threadIdx.x;
    for (int yy = threadIdx.y; yy < 32; yy += 8)
        tile[yy][x] = src[(size_t)(k0 + yy) * Nd + n0 + x];
    __syncthreads();
    for (int yy = threadIdx.y; yy < 32; yy += 8){
        float v = tile[x][yy];
        __half hi, lo; split_f32(v, hi, lo);
        size_t o = (size_t)(n0 + yy) * Kd + k0 + x;
        dh[o] = hi; dl[o] = lo;
    }
}

// ------------------------- fp16-split GEMM --------------------------------
// CTA 128x128, 8 warps (4M x 2N), warp tile 32x64. KC=32, 2-stage cp.async, occ=2.
// D = A_hi*B_hi + A_hi*B_lo + A_lo*B_hi  (fp32 accumulate)
#define ROWB 80
#define TILEB 10240
#define STG   40960
#define SMEM_DYN (2*STG)

__global__ void __launch_bounds__(256, 2) gemm_fp16s(
    int a_id, size_t a_tstr, int lda, int K,
    int b_id, const float* __restrict__ bias,
    int aux_id, int out_id, int Ntot, int epi)
{
    extern __shared__ char smem[];
    uint32_t sb = smem_u32(smem);
    int tid = threadIdx.x, wid = tid >> 5, lid = tid & 31;
    int warp_m = wid & 3, warp_n = wid >> 2;
    int t  = blockIdx.z;
    int m0 = blockIdx.x * 128;
    int n0 = blockIdx.y * 128;

    const __half* Ah = get_hbuf(a_id, 0) + (size_t)t * a_tstr + (size_t)m0 * lda;
    const __half* Al = get_hbuf(a_id, 1) + (size_t)t * a_tstr + (size_t)m0 * lda;
    const __half* Bh = get_hbuf(b_id, 0) + ((size_t)t * Ntot + n0) * K;
    const __half* Bl = get_hbuf(b_id, 1) + ((size_t)t * Ntot + n0) * K;

    float acc[2][8][4];
    #pragma unroll
    for (int mi = 0; mi < 2; mi++)
        #pragma unroll
        for (int ni = 0; ni < 8; ni++)
            #pragma unroll
            for (int j = 0; j < 4; j++) acc[mi][ni][j] = 0.f;

    int nk = K >> 5;

    int lq = lid >> 3, lr = lid & 7;
    uint32_t a_row_base = (uint32_t)(warp_m * 32 + ((lq & 1) << 3) + lr);
    uint32_t a_colb     = (uint32_t)((lq >> 1) << 4);
    uint32_t b_row_base = (uint32_t)(warp_n * 64 + ((lq >> 1) << 3) + lr);
    uint32_t b_colb     = (uint32_t)((lq & 1) << 4);

    // hoisted per-thread loader: fixed tile per thread (64 threads each)
    int l_tile = tid >> 6;            // 0..3 : Ah, Al, Bh, Bl
    int l_rem  = tid & 63;
    const __half* l_src0 = (l_tile == 0) ? Ah : (l_tile == 1) ? Al : (l_tile == 2) ? Bh : Bl;
    int l_ld = (l_tile < 2) ? lda : K;
    uint32_t l_dstbase = sb + (uint32_t)l_tile * TILEB;

    auto load_chunk = [&](int kc, int stage_sel){
        uint32_t stage = (uint32_t)stage_sel * (uint32_t)STG;
        const __half* src = l_src0 + kc * 32;
        #pragma unroll
        for (int it = 0; it < 8; it++){
            int slot = it * 64 + l_rem;
            int row  = slot >> 2, c = slot & 3;
            cp16(l_dstbase + stage + (uint32_t)row * ROWB + (uint32_t)c * 16,
                 src + (size_t)row * l_ld + c * 8);
        }
        CP_COMMIT();
    };

    load_chunk(0, 0);

    for (int kc = 0; kc < nk; kc++){
        if (kc + 1 < nk){
            load_chunk(kc + 1, (kc + 1) & 1);
            asm volatile("cp.async.wait_group 1;" ::: "memory");
        } else {
            asm volatile("cp.async.wait_group 0;" ::: "memory");
        }
        __syncthreads();

        uint32_t stg_b = sb + (uint32_t)(kc & 1) * STG;
        uint32_t sAh = stg_b;
        uint32_t sAl = stg_b + TILEB;
        uint32_t sBh = stg_b + 2 * TILEB;
        uint32_t sBl = stg_b + 3 * TILEB;

        #pragma unroll
        for (int s = 0; s < 2; s++){
            uint32_t scol = (uint32_t)(s * 32);
            uint32_t ah[2][4], al[2][4];
            #pragma unroll
            for (int mi = 0; mi < 2; mi++){
                uint32_t aoff = (a_row_base + (uint32_t)(mi * 16)) * ROWB + scol + a_colb;
                LDSM_X4(ah[mi][0], ah[mi][1], ah[mi][2], ah[mi][3], sAh + aoff);
                LDSM_X4(al[mi][0], al[mi][1], al[mi][2], al[mi][3], sAl + aoff);
            }
            #pragma unroll
            for (int p = 0; p < 4; p++){
                uint32_t boff = (b_row_base + (uint32_t)(p * 16)) * ROWB + scol + b_colb;
                uint32_t bh0, bh1, bh2, bh3, bl0, bl1, bl2, bl3;
                LDSM_X4(bh0, bh1, bh2, bh3, sBh + boff);
                LDSM_X4(bl0, bl1, bl2, bl3, sBl + boff);
                #pragma unroll
                for (int mi = 0; mi < 2; mi++){
                    MMA16816(acc[mi][2*p],   ah[mi], bh0, bh1);
                    MMA16816(acc[mi][2*p],   ah[mi], bl0, bl1);
                    MMA16816(acc[mi][2*p],   al[mi], bh0, bh1);
                    MMA16816(acc[mi][2*p+1], ah[mi], bh2, bh3);
                    MMA16816(acc[mi][2*p+1], ah[mi], bl2, bl3);
                    MMA16816(acc[mi][2*p+1], al[mi], bh2, bh3);
                }
            }
        }
        __syncthreads();
    }

    // ---------------- epilogue ----------------
    const float* biasp = bias + (size_t)t * Ntot;
    const __half* axh = nullptr; const __half* axl = nullptr;
    if (epi){
        axh = get_hbuf(aux_id, 0) + (size_t)t * BB * Ntot;
        axl = get_hbuf(aux_id, 1) + (size_t)t * BB * Ntot;
    }
    __half* oh = get_hbuf(out_id, 0) + (size_t)t * BB * Ntot;
    __half* ol = get_hbuf(out_id, 1) + (size_t)t * BB * Ntot;

    int g = lid >> 2, tig = lid & 3;
    #pragma unroll
    for (int mi = 0; mi < 2; mi++){
        #pragma unroll
        for (int ni = 0; ni < 8; ni++){
            int col = n0 + warp_n * 64 + ni * 8 + 2 * tig;
            float2 bv = *(const float2*)(biasp + col);
            int row0 = m0 + warp_m * 32 + mi * 16 + g;
            #pragma unroll
            for (int h = 0; h < 2; h++){
                int row = row0 + h * 8;
                size_t off = (size_t)row * Ntot + col;
                float v0 = acc[mi][ni][2*h]   + bv.x;
                float v1 = acc[mi][ni][2*h+1] + bv.y;
                float a0 = 0.f, a1 = 0.f;
                if (epi){
                    __half2 hv = *(const __half2*)(axh + off);
                    __half2 lv = *(const __half2*)(axl + off);
                    a0 = __half2float(hv.x) + __half2float(lv.x);
                    a1 = __half2float(hv.y) + __half2float(lv.y);
                }
                float r0, r1;
                if (epi == 0){
                    r0 = fmaxf(v0, 0.f); r1 = fmaxf(v1, 0.f);
                } else if (epi == 1){
                    r0 = a0 * (1.f / (1.f + __expf(-2.f * v0)));
                    r1 = a1 * (1.f / (1.f + __expf(-2.f * v1)));
                } else {
                    r0 = fmaxf(v0 * a0, 0.f); r1 = fmaxf(v1 * a1, 0.f);
                }
                __half h0v, l0v, h1v, l1v;
                split_f32(r0, h0v, l0v); split_f32(r1, h1v, l1v);
                *(__half2*)(oh + off) = __halves2half2(h0v, h1v);
                *(__half2*)(ol + off) = __halves2half2(l0v, l1v);
            }
        }
    }
}

// ------------------------- output layer -----------------------------------
__global__ void out_k(const float* __restrict__ W2, const float* __restrict__ b2,
                      float* __restrict__ out){
    int b = blockIdx.x;
    int wid = threadIdx.x >> 5, lid = threadIdx.x & 31;   // wid = task
    const __half* xh = get_hbuf(HP_X1, 0) + ((size_t)wid * BB + b) * H1;
    const __half* xl = get_hbuf(HP_X1, 1) + ((size_t)wid * BB + b) * H1;
    const float* wr = W2 + (size_t)wid * H1;
    float s = 0.f;
    #pragma unroll
    for (int j = 0; j < 8; j++){
        int i = lid + 32 * j;
        s += (__half2float(xh[i]) + __half2float(xl[i])) * wr[i];
    }
    #pragma unroll
    for (int o = 16; o > 0; o >>= 1)
        s += __shfl_down_sync(0xFFFFFFFFu, s, o);
    if (lid == 0) out[(size_t)b * TT + wid] = s + b2[wid];
}

// ------------------------- launch -----------------------------------------
extern "C" void kernel_launch(void* const* d_in, const int* in_sizes, int n_in,
                              void* d_out, int out_size) {
    const float* prior    = (const float*)d_in[0];
    const float* gen      = (const float*)d_in[1];
    const float* pers     = (const float*)d_in[2];
    const float* tower_W0 = (const float*)d_in[3];
    const float* tower_b0 = (const float*)d_in[4];
    const float* tower_W1 = (const float*)d_in[5];
    const float* tower_b1 = (const float*)d_in[6];
    const float* tower_W2 = (const float*)d_in[7];
    const float* tower_b2 = (const float*)d_in[8];
    const float* ppn0_W   = (const float*)d_in[9];
    const float* ppn0_b   = (const float*)d_in[10];
    const float* gate0_W  = (const float*)d_in[11];
    const float* gate0_b  = (const float*)d_in[12];
    const float* ppn1_W   = (const float*)d_in[13];
    const float* ppn1_b   = (const float*)d_in[14];
    const float* gate1_W  = (const float*)d_in[15];
    const float* gate1_b  = (const float*)d_in[16];

    cudaFuncSetAttribute(gemm_fp16s,
                         cudaFuncAttributeMaxDynamicSharedMemorySize, SMEM_DYN);

    // launches 0,1,2: prep — so launch index 5 (ncu -s 5 -c 1) is tower0 GEMM
    concat_convert_k<<<(BB * CCH) / 256, 256>>>(prior, gen);
    pers_convert_k<<<(BB * GGD) / 256, 256>>>(pers);
    transpose_all_k<<<dim3(1280, 1, TT), dim3(32, 8)>>>(
        ppn0_W, gate0_W, tower_W0, ppn1_W, gate1_W, tower_W1);

    // ppn0: h0 = relu(comb @ W + b)                 [K=768, N=512]   launch 3
    gemm_fp16s<<<dim3(BB/128, H0/128, TT), 256, SMEM_DYN>>>(
        HP_COMB, 0, CCH, CCH, HP_WPPN0, ppn0_b, 0, HP_H0, H0, 0);
    // gate0: g0 = h0 * sigmoid(2*(h0 @ Wg + b))     [K=512, N=512]   launch 4
    gemm_fp16s<<<dim3(BB/128, H0/128, TT), 256, SMEM_DYN>>>(
        HP_H0, (size_t)BB*H0, H0, H0, HP_WGT0, gate0_b, HP_H0, HP_G0, H0, 1);
    // tower0: x0 = relu((pers @ W0 + b0) * g0)      [K=512, N=512]   launch 5 (profiled)
    gemm_fp16s<<<dim3(BB/128, H0/128, TT), 256, SMEM_DYN>>>(
        HP_PERS, 0, GGD, GGD, HP_WTW0, tower_b0, HP_G0, HP_X0, H0, 2);
    // ppn1: h1 = relu(comb @ W + b)                 [K=768, N=256]
    gemm_fp16s<<<dim3(BB/128, H1/128, TT), 256, SMEM_DYN>>>(
        HP_COMB, 0, CCH, CCH, HP_WPPN1, ppn1_b, 0, HP_H1, H1, 0);
    // gate1: g1 = h1 * sigmoid(2*(h1 @ Wg + b))     [K=256, N=256]
    gemm_fp16s<<<dim3(BB/128, H1/128, TT), 256, SMEM_DYN>>>(
        HP_H1, (size_t)BB*H1, H1, H1, HP_WGT1, gate1_b, HP_H1, HP_G1, H1, 1);
    // tower1: x1 = relu((x0 @ W1 + b1) * g1)        [K=512, N=256]
    gemm_fp16s<<<dim3(BB/128, H1/128, TT), 256, SMEM_DYN>>>(
        HP_X0, (size_t)BB*H0, H0, H0, HP_WTW1, tower_b1, HP_G1, HP_X1, H1, 2);

    out_k<<<BB, 256>>>(tower_W2, tower_b2, (float*)d_out);
}

// round 9
// speedup vs baseline: 1.4732x; 1.1361x over previous
#include <cuda_runtime.h>
#include <cuda_fp16.h>
#include <cstdint>
#include <cstddef>

#define BB  8192
#define TT  8
#define PPD 256
#define GGD 512
#define CCH 768
#define H0  512
#define H1  256

// ------------------------- device scratch (352 MB total) -------------------
__device__ __align__(256) __half g_comb_h [(size_t)BB*CCH];
__device__ __align__(256) __half g_comb_l [(size_t)BB*CCH];
__device__ __align__(256) __half g_pers_h [(size_t)BB*GGD];
__device__ __align__(256) __half g_pers_l [(size_t)BB*GGD];
__device__ __align__(256) __half g_wppn0_h[(size_t)TT*H0*CCH];
__device__ __align__(256) __half g_wppn0_l[(size_t)TT*H0*CCH];
__device__ __align__(256) __half g_wgt0_h [(size_t)TT*H0*H0];
__device__ __align__(256) __half g_wgt0_l [(size_t)TT*H0*H0];
__device__ __align__(256) __half g_wtw0_h [(size_t)TT*H0*GGD];
__device__ __align__(256) __half g_wtw0_l [(size_t)TT*H0*GGD];
__device__ __align__(256) __half g_wppn1_h[(size_t)TT*H1*CCH];
__device__ __align__(256) __half g_wppn1_l[(size_t)TT*H1*CCH];
__device__ __align__(256) __half g_wgt1_h [(size_t)TT*H1*H1];
__device__ __align__(256) __half g_wgt1_l [(size_t)TT*H1*H1];
__device__ __align__(256) __half g_wtw1_h [(size_t)TT*H1*H0];
__device__ __align__(256) __half g_wtw1_l [(size_t)TT*H1*H0];

// Aliased activation pools (stream order makes every overwrite safe; see R5/R6)
#define P64  67108864ull
#define P32  33554432ull
__device__ __align__(256) unsigned char g_poolA[2ull*P64];
__device__ __align__(256) unsigned char g_poolB[2ull*P64];

enum { HP_COMB=0, HP_PERS, HP_WPPN0, HP_WGT0, HP_WTW0, HP_WPPN1, HP_WGT1, HP_WTW1,
       HP_H0, HP_X0, HP_G0, HP_H1, HP_G1, HP_X1 };

__device__ __forceinline__ __half* get_hbuf(int id, int plane){
    switch(id){
        case HP_COMB:  return plane ? g_comb_l  : g_comb_h;
        case HP_PERS:  return plane ? g_pers_l  : g_pers_h;
        case HP_WPPN0: return plane ? g_wppn0_l : g_wppn0_h;
        case HP_WGT0:  return plane ? g_wgt0_l  : g_wgt0_h;
        case HP_WTW0:  return plane ? g_wtw0_l  : g_wtw0_h;
        case HP_WPPN1: return plane ? g_wppn1_l : g_wppn1_h;
        case HP_WGT1:  return plane ? g_wgt1_l  : g_wgt1_h;
        case HP_WTW1:  return plane ? g_wtw1_l  : g_wtw1_h;
        case HP_H0:    return (__half*)(g_poolA + (plane ? P64 : 0));
        case HP_X0:    return (__half*)(g_poolA + (plane ? P64 : 0));
        case HP_G0:    return (__half*)(g_poolB + (plane ? P64 : 0));
        case HP_H1:    return (__half*)(g_poolB + (plane ? P32 : 0));
        case HP_G1:    return (__half*)(g_poolB + P64 + (plane ? P32 : 0));
        default:       return (__half*)(g_poolB + (plane ? P32 : 0));   // HP_X1
    }
}

// ------------------------- small helpers ----------------------------------
__device__ __forceinline__ uint32_t smem_u32(const void* p){
    uint32_t a;
    asm("{ .reg .u64 t; cvta.to.shared.u64 t, %1; cvt.u32.u64 %0, t; }" : "=r"(a) : "l"(p));
    return a;
}
__device__ __forceinline__ void split_f32(float v, __half& hi, __half& lo){
    hi = __float2half_rn(v);
    lo = __float2half_rn(v - __half2float(hi));
}
__device__ __forceinline__ void cp16(uint32_t dst, const void* src){
    asm volatile("cp.async.cg.shared.global [%0], [%1], 16;" :: "r"(dst), "l"(src));
}
#define CP_COMMIT() asm volatile("cp.async.commit_group;" ::: "memory")
// SW64 swizzle: bits [5:4] ^= bits [8:7]  -> conflict-free ldmatrix at 64B rows
__device__ __forceinline__ uint32_t sw64(uint32_t off){ return off ^ ((off >> 3) & 0x30); }
#define LDSM_X4(r0,r1,r2,r3,addr) \
    asm volatile("ldmatrix.sync.aligned.m8n8.x4.shared.b16 {%0,%1,%2,%3}, [%4];" \
        : "=r"(r0), "=r"(r1), "=r"(r2), "=r"(r3) : "r"(addr))
#define MMA16816(d, a, b0, b1) \
    asm volatile("mma.sync.aligned.m16n8k16.row.col.f32.f16.f16.f32 " \
        "{%0,%1,%2,%3}, {%4,%5,%6,%7}, {%8,%9}, {%0,%1,%2,%3};" \
        : "+f"((d)[0]), "+f"((d)[1]), "+f"((d)[2]), "+f"((d)[3]) \
        : "r"((a)[0]), "r"((a)[1]), "r"((a)[2]), "r"((a)[3]), "r"(b0), "r"(b1))

// ------------------------- prep kernels -----------------------------------
__global__ void concat_convert_k(const float* __restrict__ prior, const float* __restrict__ gen){
    int i = blockIdx.x * blockDim.x + threadIdx.x;
    if (i >= BB * CCH) return;
    int b = i / CCH, c = i % CCH;
    float v = (c < PPD) ? prior[(size_t)b * PPD + c] : gen[(size_t)b * GGD + (c - PPD)];
    __half hi, lo; split_f32(v, hi, lo);
    g_comb_h[i] = hi; g_comb_l[i] = lo;
}
__global__ void pers_convert_k(const float* __restrict__ pers){
    int i = blockIdx.x * blockDim.x + threadIdx.x;
    if (i >= BB * GGD) return;
    __half hi, lo; split_f32(pers[i], hi, lo);
    g_pers_h[i] = hi; g_pers_l[i] = lo;
}

// One fused kernel transposes+converts ALL six weights.
__global__ void transpose_all_k(const float* __restrict__ Wp0, const float* __restrict__ Wg0,
                                const float* __restrict__ Wt0, const float* __restrict__ Wp1,
                                const float* __restrict__ Wg1, const float* __restrict__ Wt1){
    __shared__ float tile[32][33];
    int t = blockIdx.z;
    int bid = blockIdx.x;
    const float* src; __half* dh; __half* dl; int Kd, Nd, idx;
    if      (bid < 384)  { src=Wp0; dh=g_wppn0_h; dl=g_wppn0_l; Kd=CCH; Nd=H0; idx=bid; }
    else if (bid < 640)  { src=Wg0; dh=g_wgt0_h;  dl=g_wgt0_l;  Kd=H0;  Nd=H0; idx=bid-384; }
    else if (bid < 896)  { src=Wt0; dh=g_wtw0_h;  dl=g_wtw0_l;  Kd=GGD; Nd=H0; idx=bid-640; }
    else if (bid < 1088) { src=Wp1; dh=g_wppn1_h; dl=g_wppn1_l; Kd=CCH; Nd=H1; idx=bid-896; }
    else if (bid < 1152) { src=Wg1; dh=g_wgt1_h;  dl=g_wgt1_l;  Kd=H1;  Nd=H1; idx=bid-1088; }
    else                 { src=Wt1; dh=g_wtw1_h;  dl=g_wtw1_l;  Kd=H0;  Nd=H1; idx=bid-1152; }
    int kt = Kd / 32;
    int k0 = (idx % kt) * 32, n0 = (idx / kt) * 32;
    src += (size_t)t * Kd * Nd;
    dh  += (size_t)t * Nd * Kd;
    dl  += (size_t)t * Nd * Kd;
    int x = threadIdx.x;
    for (int yy = threadIdx.y; yy < 32; yy += 8)
        tile[yy][x] = src[(size_t)(k0 + yy) * Nd + n0 + x];
    __syncthreads();
    for (int yy = threadIdx.y; yy < 32; yy += 8){
        float v = tile[x][yy];
        __half hi, lo; split_f32(v, hi, lo);
        size_t o = (size_t)(n0 + yy) * Kd + k0 + x;
        dh[o] = hi; dl[o] = lo;
    }
}

// ------------------------- fp16-split GEMM --------------------------------
// CTA 128x128, 8 warps (4M x 2N), warp tile 32x64. KC=32.
// 3-stage cp.async multistage, ONE __syncthreads per chunk, SW64-swizzled SMEM.
// D = A_hi*B_hi + A_hi*B_lo + A_lo*B_hi  (fp32 accumulate)
#define ROWB 64
#define TILEB 8192
#define STG   32768
#define NSTAGE 3
#define SMEM_DYN (NSTAGE*STG)

__global__ void __launch_bounds__(256, 2) gemm_fp16s(
    int a_id, size_t a_tstr, int lda, int K,
    int b_id, const float* __restrict__ bias,
    int aux_id, int out_id, int Ntot, int epi)
{
    extern __shared__ char smem[];
    uint32_t sb = smem_u32(smem);
    int tid = threadIdx.x, wid = tid >> 5, lid = tid & 31;
    int warp_m = wid & 3, warp_n = wid >> 2;
    int t  = blockIdx.z;
    int m0 = blockIdx.x * 128;
    int n0 = blockIdx.y * 128;

    const __half* Ah = get_hbuf(a_id, 0) + (size_t)t * a_tstr + (size_t)m0 * lda;
    const __half* Al = get_hbuf(a_id, 1) + (size_t)t * a_tstr + (size_t)m0 * lda;
    const __half* Bh = get_hbuf(b_id, 0) + ((size_t)t * Ntot + n0) * K;
    const __half* Bl = get_hbuf(b_id, 1) + ((size_t)t * Ntot + n0) * K;

    float acc[2][8][4];
    #pragma unroll
    for (int mi = 0; mi < 2; mi++)
        #pragma unroll
        for (int ni = 0; ni < 8; ni++)
            #pragma unroll
            for (int j = 0; j < 4; j++) acc[mi][ni][j] = 0.f;

    int nk = K >> 5;

    // ---- lane-constant ldmatrix offsets (swizzled), hoisted ----
    int lq = lid >> 3, lr = lid & 7;
    uint32_t a_row = (uint32_t)(warp_m * 32 + ((lq & 1) << 3) + lr);
    uint32_t a_cb  = (uint32_t)((lq >> 1) << 4);
    uint32_t b_row = (uint32_t)(warp_n * 64 + ((lq >> 1) << 3) + lr);
    uint32_t b_cb  = (uint32_t)((lq & 1) << 4);
    uint32_t aoff[2][2], boff[4][2];
    #pragma unroll
    for (int mi = 0; mi < 2; mi++)
        #pragma unroll
        for (int s = 0; s < 2; s++)
            aoff[mi][s] = sw64((a_row + mi * 16) * ROWB + s * 32 + a_cb);
    #pragma unroll
    for (int p = 0; p < 4; p++)
        #pragma unroll
        for (int s = 0; s < 2; s++)
            boff[p][s] = sw64((b_row + p * 16) * ROWB + s * 32 + b_cb);

    // ---- loader: fixed tile per thread (64 threads per tile) ----
    int l_tile = tid >> 6;            // 0..3 : Ah, Al, Bh, Bl
    int l_rem  = tid & 63;
    const __half* l_src0 = (l_tile == 0) ? Ah : (l_tile == 1) ? Al : (l_tile == 2) ? Bh : Bl;
    int l_ld = (l_tile < 2) ? lda : K;
    uint32_t l_dstbase = sb + (uint32_t)l_tile * TILEB;

    auto load_chunk = [&](int kc, int stage_sel){
        uint32_t stg = (uint32_t)stage_sel * (uint32_t)STG;
        const __half* src = l_src0 + kc * 32;
        #pragma unroll
        for (int it = 0; it < 8; it++){
            int slot = it * 64 + l_rem;
            int row  = slot >> 2, c = slot & 3;
            cp16(l_dstbase + stg + sw64((uint32_t)(row * ROWB + c * 16)),
                 src + (size_t)row * l_ld + c * 8);
        }
        CP_COMMIT();
    };

    load_chunk(0, 0);
    load_chunk(1, 1);

    int stage = 0;
    for (int kc = 0; kc < nk; kc++){
        if (kc + 1 < nk)
            asm volatile("cp.async.wait_group 1;" ::: "memory");
        else
            asm volatile("cp.async.wait_group 0;" ::: "memory");
        __syncthreads();
        // prefetch kc+2 into stage (kc+2)%3 — safe: all warps passed the barrier,
        // so reads of that stage (iteration kc-1) are complete.
        if (kc + 2 < nk)
            load_chunk(kc + 2, (stage + 2 >= NSTAGE) ? stage + 2 - NSTAGE : stage + 2);

        uint32_t stg_b = sb + (uint32_t)stage * STG;
        uint32_t sAh = stg_b;
        uint32_t sAl = stg_b + TILEB;
        uint32_t sBh = stg_b + 2 * TILEB;
        uint32_t sBl = stg_b + 3 * TILEB;

        #pragma unroll
        for (int s = 0; s < 2; s++){
            uint32_t ah[2][4], al[2][4];
            #pragma unroll
            for (int mi = 0; mi < 2; mi++){
                LDSM_X4(ah[mi][0], ah[mi][1], ah[mi][2], ah[mi][3], sAh + aoff[mi][s]);
                LDSM_X4(al[mi][0], al[mi][1], al[mi][2], al[mi][3], sAl + aoff[mi][s]);
            }
            #pragma unroll
            for (int p = 0; p < 4; p++){
                uint32_t bh0, bh1, bh2, bh3, bl0, bl1, bl2, bl3;
                LDSM_X4(bh0, bh1, bh2, bh3, sBh + boff[p][s]);
                LDSM_X4(bl0, bl1, bl2, bl3, sBl + boff[p][s]);
                #pragma unroll
                for (int mi = 0; mi < 2; mi++){
                    MMA16816(acc[mi][2*p],   ah[mi], bh0, bh1);
                    MMA16816(acc[mi][2*p],   ah[mi], bl0, bl1);
                    MMA16816(acc[mi][2*p],   al[mi], bh0, bh1);
                    MMA16816(acc[mi][2*p+1], ah[mi], bh2, bh3);
                    MMA16816(acc[mi][2*p+1], ah[mi], bl2, bl3);
                    MMA16816(acc[mi][2*p+1], al[mi], bh2, bh3);
                }
            }
        }
        stage = (stage + 1 >= NSTAGE) ? 0 : stage + 1;
    }

    // ---------------- epilogue ----------------
    const float* biasp = bias + (size_t)t * Ntot;
    const __half* axh = nullptr; const __half* axl = nullptr;
    if (epi){
        axh = get_hbuf(aux_id, 0) + (size_t)t * BB * Ntot;
        axl = get_hbuf(aux_id, 1) + (size_t)t * BB * Ntot;
    }
    __half* oh = get_hbuf(out_id, 0) + (size_t)t * BB * Ntot;
    __half* ol = get_hbuf(out_id, 1) + (size_t)t * BB * Ntot;

    int g = lid >> 2, tig = lid & 3;
    #pragma unroll
    for (int mi = 0; mi < 2; mi++){
        #pragma unroll
        for (int ni = 0; ni < 8; ni++){
            int col = n0 + warp_n * 64 + ni * 8 + 2 * tig;
            float2 bv = *(const float2*)(biasp + col);
            int row0 = m0 + warp_m * 32 + mi * 16 + g;
            #pragma unroll
            for (int h = 0; h < 2; h++){
                int row = row0 + h * 8;
                size_t off = (size_t)row * Ntot + col;
                float v0 = acc[mi][ni][2*h]   + bv.x;
                float v1 = acc[mi][ni][2*h+1] + bv.y;
                float a0 = 0.f, a1 = 0.f;
                if (epi){
                    __half2 hv = *(const __half2*)(axh + off);
                    __half2 lv = *(const __half2*)(axl + off);
                    a0 = __half2float(hv.x) + __half2float(lv.x);
                    a1 = __half2float(hv.y) + __half2float(lv.y);
                }
                float r0, r1;
                if (epi == 0){
                    r0 = fmaxf(v0, 0.f); r1 = fmaxf(v1, 0.f);
                } else if (epi == 1){
                    r0 = a0 * (1.f / (1.f + __expf(-2.f * v0)));
                    r1 = a1 * (1.f / (1.f + __expf(-2.f * v1)));
                } else {
                    r0 = fmaxf(v0 * a0, 0.f); r1 = fmaxf(v1 * a1, 0.f);
                }
                __half h0v, l0v, h1v, l1v;
                split_f32(r0, h0v, l0v); split_f32(r1, h1v, l1v);
                *(__half2*)(oh + off) = __halves2half2(h0v, h1v);
                *(__half2*)(ol + off) = __halves2half2(l0v, l1v);
            }
        }
    }
}

// ------------------------- output layer -----------------------------------
__global__ void out_k(const float* __restrict__ W2, const float* __restrict__ b2,
                      float* __restrict__ out){
    int b = blockIdx.x;
    int wid = threadIdx.x >> 5, lid = threadIdx.x & 31;   // wid = task
    const __half* xh = get_hbuf(HP_X1, 0) + ((size_t)wid * BB + b) * H1;
    const __half* xl = get_hbuf(HP_X1, 1) + ((size_t)wid * BB + b) * H1;
    const float* wr = W2 + (size_t)wid * H1;
    float s = 0.f;
    #pragma unroll
    for (int j = 0; j < 8; j++){
        int i = lid + 32 * j;
        s += (__half2float(xh[i]) + __half2float(xl[i])) * wr[i];
    }
    #pragma unroll
    for (int o = 16; o > 0; o >>= 1)
        s += __shfl_down_sync(0xFFFFFFFFu, s, o);
    if (lid == 0) out[(size_t)b * TT + wid] = s + b2[wid];
}

// ------------------------- launch -----------------------------------------
extern "C" void kernel_launch(void* const* d_in, const int* in_sizes, int n_in,
                              void* d_out, int out_size) {
    const float* prior    = (const float*)d_in[0];
    const float* gen      = (const float*)d_in[1];
    const float* pers     = (const float*)d_in[2];
    const float* tower_W0 = (const float*)d_in[3];
    const float* tower_b0 = (const float*)d_in[4];
    const float* tower_W1 = (const float*)d_in[5];
    const float* tower_b1 = (const float*)d_in[6];
    const float* tower_W2 = (const float*)d_in[7];
    const float* tower_b2 = (const float*)d_in[8];
    const float* ppn0_W   = (const float*)d_in[9];
    const float* ppn0_b   = (const float*)d_in[10];
    const float* gate0_W  = (const float*)d_in[11];
    const float* gate0_b  = (const float*)d_in[12];
    const float* ppn1_W   = (const float*)d_in[13];
    const float* ppn1_b   = (const float*)d_in[14];
    const float* gate1_W  = (const float*)d_in[15];
    const float* gate1_b  = (const float*)d_in[16];

    cudaFuncSetAttribute(gemm_fp16s,
                         cudaFuncAttributeMaxDynamicSharedMemorySize, SMEM_DYN);

    // launches 0,1,2: prep — launch index 5 (ncu -s 5 -c 1) is tower0 GEMM
    concat_convert_k<<<(BB * CCH) / 256, 256>>>(prior, gen);
    pers_convert_k<<<(BB * GGD) / 256, 256>>>(pers);
    transpose_all_k<<<dim3(1280, 1, TT), dim3(32, 8)>>>(
        ppn0_W, gate0_W, tower_W0, ppn1_W, gate1_W, tower_W1);

    // ppn0: h0 = relu(comb @ W + b)                 [K=768, N=512]   launch 3
    gemm_fp16s<<<dim3(BB/128, H0/128, TT), 256, SMEM_DYN>>>(
        HP_COMB, 0, CCH, CCH, HP_WPPN0, ppn0_b, 0, HP_H0, H0, 0);
    // gate0: g0 = h0 * sigmoid(2*(h0 @ Wg + b))     [K=512, N=512]   launch 4
    gemm_fp16s<<<dim3(BB/128, H0/128, TT), 256, SMEM_DYN>>>(
        HP_H0, (size_t)BB*H0, H0, H0, HP_WGT0, gate0_b, HP_H0, HP_G0, H0, 1);
    // tower0: x0 = relu((pers @ W0 + b0) * g0)      [K=512, N=512]   launch 5 (profiled)
    gemm_fp16s<<<dim3(BB/128, H0/128, TT), 256, SMEM_DYN>>>(
        HP_PERS, 0, GGD, GGD, HP_WTW0, tower_b0, HP_G0, HP_X0, H0, 2);
    // ppn1: h1 = relu(comb @ W + b)                 [K=768, N=256]
    gemm_fp16s<<<dim3(BB/128, H1/128, TT), 256, SMEM_DYN>>>(
        HP_COMB, 0, CCH, CCH, HP_WPPN1, ppn1_b, 0, HP_H1, H1, 0);
    // gate1: g1 = h1 * sigmoid(2*(h1 @ Wg + b))     [K=256, N=256]
    gemm_fp16s<<<dim3(BB/128, H1/128, TT), 256, SMEM_DYN>>>(
        HP_H1, (size_t)BB*H1, H1, H1, HP_WGT1, gate1_b, HP_H1, HP_G1, H1, 1);
    // tower1: x1 = relu((x0 @ W1 + b1) * g1)        [K=512, N=256]
    gemm_fp16s<<<dim3(BB/128, H1/128, TT), 256, SMEM_DYN>>>(
        HP_X0, (size_t)BB*H0, H0, H0, HP_WTW1, tower_b1, HP_G1, HP_X1, H1, 2);

    out_k<<<BB, 256>>>(tower_W2, tower_b2, (float*)d_out);
}

// round 10
// speedup vs baseline: 1.4819x; 1.0060x over previous
#include <cuda_runtime.h>
#include <cuda_fp16.h>
#include <cstdint>
#include <cstddef>

#define BB  8192
#define TT  8
#define PPD 256
#define GGD 512
#define CCH 768
#define H0  512
#define H1  256

// ------------------------- device scratch (352 MB total) -------------------
__device__ __align__(256) __half g_comb_h [(size_t)BB*CCH];
__device__ __align__(256) __half g_comb_l [(size_t)BB*CCH];
__device__ __align__(256) __half g_pers_h [(size_t)BB*GGD];
__device__ __align__(256) __half g_pers_l [(size_t)BB*GGD];
__device__ __align__(256) __half g_wppn0_h[(size_t)TT*H0*CCH];
__device__ __align__(256) __half g_wppn0_l[(size_t)TT*H0*CCH];
__device__ __align__(256) __half g_wgt0_h [(size_t)TT*H0*H0];
__device__ __align__(256) __half g_wgt0_l [(size_t)TT*H0*H0];
__device__ __align__(256) __half g_wtw0_h [(size_t)TT*H0*GGD];
__device__ __align__(256) __half g_wtw0_l [(size_t)TT*H0*GGD];
__device__ __align__(256) __half g_wppn1_h[(size_t)TT*H1*CCH];
__device__ __align__(256) __half g_wppn1_l[(size_t)TT*H1*CCH];
__device__ __align__(256) __half g_wgt1_h [(size_t)TT*H1*H1];
__device__ __align__(256) __half g_wgt1_l [(size_t)TT*H1*H1];
__device__ __align__(256) __half g_wtw1_h [(size_t)TT*H1*H0];
__device__ __align__(256) __half g_wtw1_l [(size_t)TT*H1*H0];

// Aliased activation pools (stream order makes every overwrite safe; see R5/R6)
#define P64  67108864ull
#define P32  33554432ull
__device__ __align__(256) unsigned char g_poolA[2ull*P64];
__device__ __align__(256) unsigned char g_poolB[2ull*P64];

enum { HP_COMB=0, HP_PERS, HP_WPPN0, HP_WGT0, HP_WTW0, HP_WPPN1, HP_WGT1, HP_WTW1,
       HP_H0, HP_X0, HP_G0, HP_H1, HP_G1, HP_X1 };

__device__ __forceinline__ __half* get_hbuf(int id, int plane){
    switch(id){
        case HP_COMB:  return plane ? g_comb_l  : g_comb_h;
        case HP_PERS:  return plane ? g_pers_l  : g_pers_h;
        case HP_WPPN0: return plane ? g_wppn0_l : g_wppn0_h;
        case HP_WGT0:  return plane ? g_wgt0_l  : g_wgt0_h;
        case HP_WTW0:  return plane ? g_wtw0_l  : g_wtw0_h;
        case HP_WPPN1: return plane ? g_wppn1_l : g_wppn1_h;
        case HP_WGT1:  return plane ? g_wgt1_l  : g_wgt1_h;
        case HP_WTW1:  return plane ? g_wtw1_l  : g_wtw1_h;
        case HP_H0:    return (__half*)(g_poolA + (plane ? P64 : 0));
        case HP_X0:    return (__half*)(g_poolA + (plane ? P64 : 0));
        case HP_G0:    return (__half*)(g_poolB + (plane ? P64 : 0));
        case HP_H1:    return (__half*)(g_poolB + (plane ? P32 : 0));
        case HP_G1:    return (__half*)(g_poolB + P64 + (plane ? P32 : 0));
        default:       return (__half*)(g_poolB + (plane ? P32 : 0));   // HP_X1
    }
}

// ------------------------- small helpers ----------------------------------
__device__ __forceinline__ uint32_t smem_u32(const void* p){
    uint32_t a;
    asm("{ .reg .u64 t; cvta.to.shared.u64 t, %1; cvt.u32.u64 %0, t; }" : "=r"(a) : "l"(p));
    return a;
}
__device__ __forceinline__ void split_f32(float v, __half& hi, __half& lo){
    hi = __float2half_rn(v);
    lo = __float2half_rn(v - __half2float(hi));
}
__device__ __forceinline__ void cp16(uint32_t dst, const void* src){
    asm volatile("cp.async.cg.shared.global [%0], [%1], 16;" :: "r"(dst), "l"(src));
}
#define CP_COMMIT() asm volatile("cp.async.commit_group;" ::: "memory")
// SW64 swizzle: bits [5:4] ^= bits [8:7]  -> conflict-free ldmatrix at 64B rows
__device__ __forceinline__ uint32_t sw64(uint32_t off){ return off ^ ((off >> 3) & 0x30); }
#define LDSM_X4(r0,r1,r2,r3,addr) \
    asm volatile("ldmatrix.sync.aligned.m8n8.x4.shared.b16 {%0,%1,%2,%3}, [%4];" \
        : "=r"(r0), "=r"(r1), "=r"(r2), "=r"(r3) : "r"(addr))
#define MMA16816(d, a, b0, b1) \
    asm volatile("mma.sync.aligned.m16n8k16.row.col.f32.f16.f16.f32 " \
        "{%0,%1,%2,%3}, {%4,%5,%6,%7}, {%8,%9}, {%0,%1,%2,%3};" \
        : "+f"((d)[0]), "+f"((d)[1]), "+f"((d)[2]), "+f"((d)[3]) \
        : "r"((a)[0]), "r"((a)[1]), "r"((a)[2]), "r"((a)[3]), "r"(b0), "r"(b1))

// ------------------------- prep kernels -----------------------------------
__global__ void concat_convert_k(const float* __restrict__ prior, const float* __restrict__ gen){
    int i = blockIdx.x * blockDim.x + threadIdx.x;
    if (i >= BB * CCH) return;
    int b = i / CCH, c = i % CCH;
    float v = (c < PPD) ? prior[(size_t)b * PPD + c] : gen[(size_t)b * GGD + (c - PPD)];
    __half hi, lo; split_f32(v, hi, lo);
    g_comb_h[i] = hi; g_comb_l[i] = lo;
}
__global__ void pers_convert_k(const float* __restrict__ pers){
    int i = blockIdx.x * blockDim.x + threadIdx.x;
    if (i >= BB * GGD) return;
    __half hi, lo; split_f32(pers[i], hi, lo);
    g_pers_h[i] = hi; g_pers_l[i] = lo;
}

// One fused kernel transposes+converts ALL six weights.
__global__ void transpose_all_k(const float* __restrict__ Wp0, const float* __restrict__ Wg0,
                                const float* __restrict__ Wt0, const float* __restrict__ Wp1,
                                const float* __restrict__ Wg1, const float* __restrict__ Wt1){
    __shared__ float tile[32][33];
    int t = blockIdx.z;
    int bid = blockIdx.x;
    const float* src; __half* dh; __half* dl; int Kd, Nd, idx;
    if      (bid < 384)  { src=Wp0; dh=g_wppn0_h; dl=g_wppn0_l; Kd=CCH; Nd=H0; idx=bid; }
    else if (bid < 640)  { src=Wg0; dh=g_wgt0_h;  dl=g_wgt0_l;  Kd=H0;  Nd=H0; idx=bid-384; }
    else if (bid < 896)  { src=Wt0; dh=g_wtw0_h;  dl=g_wtw0_l;  Kd=GGD; Nd=H0; idx=bid-640; }
    else if (bid < 1088) { src=Wp1; dh=g_wppn1_h; dl=g_wppn1_l; Kd=CCH; Nd=H1; idx=bid-896; }
    else if (bid < 1152) { src=Wg1; dh=g_wgt1_h;  dl=g_wgt1_l;  Kd=H1;  Nd=H1; idx=bid-1088; }
    else                 { src=Wt1; dh=g_wtw1_h;  dl=g_wtw1_l;  Kd=H0;  Nd=H1; idx=bid-1152; }
    int kt = Kd / 32;
    int k0 = (idx % kt) * 32, n0 = (idx / kt) * 32;
    src += (size_t)t * Kd * Nd;
    dh  += (size_t)t * Nd * Kd;
    dl  += (size_t)t * Nd * Kd;
    int x = threadIdx.x;
    for (int yy = threadIdx.y; yy < 32; yy += 8)
        tile[yy][x] = src[(size_t)(k0 + yy) * Nd + n0 + x];
    __syncthreads();
    for (int yy = threadIdx.y; yy < 32; yy += 8){
        float v = tile[x][yy];
        __half hi, lo; split_f32(v, hi, lo);
        size_t o = (size_t)(n0 + yy) * Kd + k0 + x;
        dh[o] = hi; dl[o] = lo;
    }
}

// ------------------------- fp16-split GEMM --------------------------------
// CTA 128x128, 8 warps (4M x 2N), warp tile 32x64. KC=32.
// 3-stage cp.async multistage, ONE __syncthreads per chunk, SW64-swizzled SMEM.
// three=1: D = Ah*Bh + Ah*Bl + Al*Bh ; three=0 (gates): D = Ah*Bh + Ah*Bl
// (2-term drops the Al tile entirely: no cp.async, no LDSM, no MMA for it.
//  Error ~u/sqrt(3) on z, damped by sigmoid' <= 0.5 in the epi=1 consumer.)
#define ROWB 64
#define TILEB 8192
#define STG   32768
#define NSTAGE 3
#define SMEM_DYN (NSTAGE*STG)

__global__ void __launch_bounds__(256, 2) gemm_fp16s(
    int a_id, size_t a_tstr, int lda, int K,
    int b_id, const float* __restrict__ bias,
    int aux_id, int out_id, int Ntot, int epi, int three)
{
    extern __shared__ char smem[];
    uint32_t sb = smem_u32(smem);
    int tid = threadIdx.x, wid = tid >> 5, lid = tid & 31;
    int warp_m = wid & 3, warp_n = wid >> 2;
    int t  = blockIdx.z;
    int m0 = blockIdx.x * 128;
    int n0 = blockIdx.y * 128;

    const __half* Ah = get_hbuf(a_id, 0) + (size_t)t * a_tstr + (size_t)m0 * lda;
    const __half* Al = get_hbuf(a_id, 1) + (size_t)t * a_tstr + (size_t)m0 * lda;
    const __half* Bh = get_hbuf(b_id, 0) + ((size_t)t * Ntot + n0) * K;
    const __half* Bl = get_hbuf(b_id, 1) + ((size_t)t * Ntot + n0) * K;

    float acc[2][8][4];
    #pragma unroll
    for (int mi = 0; mi < 2; mi++)
        #pragma unroll
        for (int ni = 0; ni < 8; ni++)
            #pragma unroll
            for (int j = 0; j < 4; j++) acc[mi][ni][j] = 0.f;

    int nk = K >> 5;

    // ---- lane-constant ldmatrix offsets (swizzled), hoisted ----
    int lq = lid >> 3, lr = lid & 7;
    uint32_t a_row = (uint32_t)(warp_m * 32 + ((lq & 1) << 3) + lr);
    uint32_t a_cb  = (uint32_t)((lq >> 1) << 4);
    uint32_t b_row = (uint32_t)(warp_n * 64 + ((lq >> 1) << 3) + lr);
    uint32_t b_cb  = (uint32_t)((lq & 1) << 4);
    uint32_t aoff[2][2], boff[4][2];
    #pragma unroll
    for (int mi = 0; mi < 2; mi++)
        #pragma unroll
        for (int s = 0; s < 2; s++)
            aoff[mi][s] = sw64((a_row + mi * 16) * ROWB + s * 32 + a_cb);
    #pragma unroll
    for (int p = 0; p < 4; p++)
        #pragma unroll
        for (int s = 0; s < 2; s++)
            boff[p][s] = sw64((b_row + p * 16) * ROWB + s * 32 + b_cb);

    // ---- loader: fixed tile per thread (64 threads per tile) ----
    int l_tile = tid >> 6;            // 0..3 : Ah, Al, Bh, Bl
    int l_rem  = tid & 63;
    const __half* l_src0 = (l_tile == 0) ? Ah : (l_tile == 1) ? Al : (l_tile == 2) ? Bh : Bl;
    int l_ld = (l_tile < 2) ? lda : K;
    uint32_t l_dstbase = sb + (uint32_t)l_tile * TILEB;
    bool l_active = three || (l_tile != 1);   // 2-term: skip the Al tile

    auto load_chunk = [&](int kc, int stage_sel){
        uint32_t stg = (uint32_t)stage_sel * (uint32_t)STG;
        if (l_active){
            const __half* src = l_src0 + kc * 32;
            #pragma unroll
            for (int it = 0; it < 8; it++){
                int slot = it * 64 + l_rem;
                int row  = slot >> 2, c = slot & 3;
                cp16(l_dstbase + stg + sw64((uint32_t)(row * ROWB + c * 16)),
                     src + (size_t)row * l_ld + c * 8);
            }
        }
        CP_COMMIT();
    };

    load_chunk(0, 0);
    load_chunk(1, 1);

    int stage = 0;
    for (int kc = 0; kc < nk; kc++){
        if (kc + 1 < nk)
            asm volatile("cp.async.wait_group 1;" ::: "memory");
        else
            asm volatile("cp.async.wait_group 0;" ::: "memory");
        __syncthreads();
        // prefetch kc+2 into stage (kc+2)%3 — safe: all warps passed the barrier
        if (kc + 2 < nk)
            load_chunk(kc + 2, (stage + 2 >= NSTAGE) ? stage + 2 - NSTAGE : stage + 2);

        uint32_t stg_b = sb + (uint32_t)stage * STG;
        uint32_t sAh = stg_b;
        uint32_t sAl = stg_b + TILEB;
        uint32_t sBh = stg_b + 2 * TILEB;
        uint32_t sBl = stg_b + 3 * TILEB;

        #pragma unroll
        for (int s = 0; s < 2; s++){
            uint32_t ah[2][4], al[2][4];
            #pragma unroll
            for (int mi = 0; mi < 2; mi++){
                LDSM_X4(ah[mi][0], ah[mi][1], ah[mi][2], ah[mi][3], sAh + aoff[mi][s]);
                if (three){
                    LDSM_X4(al[mi][0], al[mi][1], al[mi][2], al[mi][3], sAl + aoff[mi][s]);
                }
            }
            #pragma unroll
            for (int p = 0; p < 4; p++){
                uint32_t bh0, bh1, bh2, bh3, bl0, bl1, bl2, bl3;
                LDSM_X4(bh0, bh1, bh2, bh3, sBh + boff[p][s]);
                LDSM_X4(bl0, bl1, bl2, bl3, sBl + boff[p][s]);
                #pragma unroll
                for (int mi = 0; mi < 2; mi++){
                    MMA16816(acc[mi][2*p],   ah[mi], bh0, bh1);
                    MMA16816(acc[mi][2*p],   ah[mi], bl0, bl1);
                    MMA16816(acc[mi][2*p+1], ah[mi], bh2, bh3);
                    MMA16816(acc[mi][2*p+1], ah[mi], bl2, bl3);
                    if (three){
                        MMA16816(acc[mi][2*p],   al[mi], bh0, bh1);
                        MMA16816(acc[mi][2*p+1], al[mi], bh2, bh3);
                    }
                }
            }
        }
        stage = (stage + 1 >= NSTAGE) ? 0 : stage + 1;
    }

    // ---------------- epilogue ----------------
    const float* biasp = bias + (size_t)t * Ntot;
    const __half* axh = nullptr; const __half* axl = nullptr;
    if (epi){
        axh = get_hbuf(aux_id, 0) + (size_t)t * BB * Ntot;
        axl = get_hbuf(aux_id, 1) + (size_t)t * BB * Ntot;
    }
    __half* oh = get_hbuf(out_id, 0) + (size_t)t * BB * Ntot;
    __half* ol = get_hbuf(out_id, 1) + (size_t)t * BB * Ntot;

    int g = lid >> 2, tig = lid & 3;
    #pragma unroll
    for (int mi = 0; mi < 2; mi++){
        #pragma unroll
        for (int ni = 0; ni < 8; ni++){
            int col = n0 + warp_n * 64 + ni * 8 + 2 * tig;
            float2 bv = *(const float2*)(biasp + col);
            int row0 = m0 + warp_m * 32 + mi * 16 + g;
            #pragma unroll
            for (int h = 0; h < 2; h++){
                int row = row0 + h * 8;
                size_t off = (size_t)row * Ntot + col;
                float v0 = acc[mi][ni][2*h]   + bv.x;
                float v1 = acc[mi][ni][2*h+1] + bv.y;
                float a0 = 0.f, a1 = 0.f;
                if (epi){
                    __half2 hv = *(const __half2*)(axh + off);
                    __half2 lv = *(const __half2*)(axl + off);
                    a0 = __half2float(hv.x) + __half2float(lv.x);
                    a1 = __half2float(hv.y) + __half2float(lv.y);
                }
                float r0, r1;
                if (epi == 0){
                    r0 = fmaxf(v0, 0.f); r1 = fmaxf(v1, 0.f);
                } else if (epi == 1){
                    r0 = a0 * (1.f / (1.f + __expf(-2.f * v0)));
                    r1 = a1 * (1.f / (1.f + __expf(-2.f * v1)));
                } else {
                    r0 = fmaxf(v0 * a0, 0.f); r1 = fmaxf(v1 * a1, 0.f);
                }
                __half h0v, l0v, h1v, l1v;
                split_f32(r0, h0v, l0v); split_f32(r1, h1v, l1v);
                *(__half2*)(oh + off) = __halves2half2(h0v, h1v);
                *(__half2*)(ol + off) = __halves2half2(l0v, l1v);
            }
        }
    }
}

// ------------------------- output layer -----------------------------------
__global__ void out_k(const float* __restrict__ W2, const float* __restrict__ b2,
                      float* __restrict__ out){
    int b = blockIdx.x;
    int wid = threadIdx.x >> 5, lid = threadIdx.x & 31;   // wid = task
    const __half* xh = get_hbuf(HP_X1, 0) + ((size_t)wid * BB + b) * H1;
    const __half* xl = get_hbuf(HP_X1, 1) + ((size_t)wid * BB + b) * H1;
    const float* wr = W2 + (size_t)wid * H1;
    float s = 0.f;
    #pragma unroll
    for (int j = 0; j < 8; j++){
        int i = lid + 32 * j;
        s += (__half2float(xh[i]) + __half2float(xl[i])) * wr[i];
    }
    #pragma unroll
    for (int o = 16; o > 0; o >>= 1)
        s += __shfl_down_sync(0xFFFFFFFFu, s, o);
    if (lid == 0) out[(size_t)b * TT + wid] = s + b2[wid];
}

// ------------------------- launch -----------------------------------------
extern "C" void kernel_launch(void* const* d_in, const int* in_sizes, int n_in,
                              void* d_out, int out_size) {
    const float* prior    = (const float*)d_in[0];
    const float* gen      = (const float*)d_in[1];
    const float* pers     = (const float*)d_in[2];
    const float* tower_W0 = (const float*)d_in[3];
    const float* tower_b0 = (const float*)d_in[4];
    const float* tower_W1 = (const float*)d_in[5];
    const float* tower_b1 = (const float*)d_in[6];
    const float* tower_W2 = (const float*)d_in[7];
    const float* tower_b2 = (const float*)d_in[8];
    const float* ppn0_W   = (const float*)d_in[9];
    const float* ppn0_b   = (const float*)d_in[10];
    const float* gate0_W  = (const float*)d_in[11];
    const float* gate0_b  = (const float*)d_in[12];
    const float* ppn1_W   = (const float*)d_in[13];
    const float* ppn1_b   = (const float*)d_in[14];
    const float* gate1_W  = (const float*)d_in[15];
    const float* gate1_b  = (const float*)d_in[16];

    cudaFuncSetAttribute(gemm_fp16s,
                         cudaFuncAttributeMaxDynamicSharedMemorySize, SMEM_DYN);

    // launches 0,1,2: prep — launch index 5 (ncu -s 5 -c 1) is tower0 GEMM
    concat_convert_k<<<(BB * CCH) / 256, 256>>>(prior, gen);
    pers_convert_k<<<(BB * GGD) / 256, 256>>>(pers);
    transpose_all_k<<<dim3(1280, 1, TT), dim3(32, 8)>>>(
        ppn0_W, gate0_W, tower_W0, ppn1_W, gate1_W, tower_W1);

    // ppn0: h0 = relu(comb @ W + b)                 [K=768, N=512]   3-term
    gemm_fp16s<<<dim3(BB/128, H0/128, TT), 256, SMEM_DYN>>>(
        HP_COMB, 0, CCH, CCH, HP_WPPN0, ppn0_b, 0, HP_H0, H0, 0, 1);
    // gate0: g0 = h0 * sigmoid(2*(h0 @ Wg + b))     [K=512, N=512]   2-term (damped)
    gemm_fp16s<<<dim3(BB/128, H0/128, TT), 256, SMEM_DYN>>>(
        HP_H0, (size_t)BB*H0, H0, H0, HP_WGT0, gate0_b, HP_H0, HP_G0, H0, 1, 0);
    // tower0: x0 = relu((pers @ W0 + b0) * g0)      [K=512, N=512]   3-term (profiled)
    gemm_fp16s<<<dim3(BB/128, H0/128, TT), 256, SMEM_DYN>>>(
        HP_PERS, 0, GGD, GGD, HP_WTW0, tower_b0, HP_G0, HP_X0, H0, 2, 1);
    // ppn1: h1 = relu(comb @ W + b)                 [K=768, N=256]   3-term
    gemm_fp16s<<<dim3(BB/128, H1/128, TT), 256, SMEM_DYN>>>(
        HP_COMB, 0, CCH, CCH, HP_WPPN1, ppn1_b, 0, HP_H1, H1, 0, 1);
    // gate1: g1 = h1 * sigmoid(2*(h1 @ Wg + b))     [K=256, N=256]   2-term (damped)
    gemm_fp16s<<<dim3(BB/128, H1/128, TT), 256, SMEM_DYN>>>(
        HP_H1, (size_t)BB*H1, H1, H1, HP_WGT1, gate1_b, HP_H1, HP_G1, H1, 1, 0);
    // tower1: x1 = relu((x0 @ W1 + b1) * g1)        [K=512, N=256]   3-term
    gemm_fp16s<<<dim3(BB/128, H1/128, TT), 256, SMEM_DYN>>>(
        HP_X0, (size_t)BB*H0, H0, H0, HP_WTW1, tower_b1, HP_G1, HP_X1, H1, 2, 1);

    out_k<<<BB, 256>>>(tower_W2, tower_b2, (float*)d_out);
}

// round 11
// speedup vs baseline: 1.5253x; 1.0292x over previous
#include <cuda_runtime.h>
#include <cuda_fp16.h>
#include <cstdint>
#include <cstddef>

#define BB  8192
#define TT  8
#define PPD 256
#define GGD 512
#define CCH 768
#define H0  512
#define H1  256

// ------------------------- device scratch (352 MB total) -------------------
__device__ __align__(256) __half g_comb_h [(size_t)BB*CCH];
__device__ __align__(256) __half g_comb_l [(size_t)BB*CCH];
__device__ __align__(256) __half g_pers_h [(size_t)BB*GGD];
__device__ __align__(256) __half g_pers_l [(size_t)BB*GGD];
__device__ __align__(256) __half g_wppn0_h[(size_t)TT*H0*CCH];
__device__ __align__(256) __half g_wppn0_l[(size_t)TT*H0*CCH];
__device__ __align__(256) __half g_wgt0_h [(size_t)TT*H0*H0];
__device__ __align__(256) __half g_wgt0_l [(size_t)TT*H0*H0];
__device__ __align__(256) __half g_wtw0_h [(size_t)TT*H0*GGD];
__device__ __align__(256) __half g_wtw0_l [(size_t)TT*H0*GGD];
__device__ __align__(256) __half g_wppn1_h[(size_t)TT*H1*CCH];
__device__ __align__(256) __half g_wppn1_l[(size_t)TT*H1*CCH];
__device__ __align__(256) __half g_wgt1_h [(size_t)TT*H1*H1];
__device__ __align__(256) __half g_wgt1_l [(size_t)TT*H1*H1];
__device__ __align__(256) __half g_wtw1_h [(size_t)TT*H1*H0];
__device__ __align__(256) __half g_wtw1_l [(size_t)TT*H1*H0];

// Aliased activation pools (stream order makes every overwrite safe; see R5/R6)
#define P64  67108864ull
#define P32  33554432ull
__device__ __align__(256) unsigned char g_poolA[2ull*P64];
__device__ __align__(256) unsigned char g_poolB[2ull*P64];

enum { HP_COMB=0, HP_PERS, HP_WPPN0, HP_WGT0, HP_WTW0, HP_WPPN1, HP_WGT1, HP_WTW1,
       HP_H0, HP_X0, HP_G0, HP_H1, HP_G1, HP_X1 };

__device__ __forceinline__ __half* get_hbuf(int id, int plane){
    switch(id){
        case HP_COMB:  return plane ? g_comb_l  : g_comb_h;
        case HP_PERS:  return plane ? g_pers_l  : g_pers_h;
        case HP_WPPN0: return plane ? g_wppn0_l : g_wppn0_h;
        case HP_WGT0:  return plane ? g_wgt0_l  : g_wgt0_h;
        case HP_WTW0:  return plane ? g_wtw0_l  : g_wtw0_h;
        case HP_WPPN1: return plane ? g_wppn1_l : g_wppn1_h;
        case HP_WGT1:  return plane ? g_wgt1_l  : g_wgt1_h;
        case HP_WTW1:  return plane ? g_wtw1_l  : g_wtw1_h;
        case HP_H0:    return (__half*)(g_poolA + (plane ? P64 : 0));
        case HP_X0:    return (__half*)(g_poolA + (plane ? P64 : 0));
        case HP_G0:    return (__half*)(g_poolB + (plane ? P64 : 0));
        case HP_H1:    return (__half*)(g_poolB + (plane ? P32 : 0));
        case HP_G1:    return (__half*)(g_poolB + P64 + (plane ? P32 : 0));
        default:       return (__half*)(g_poolB + (plane ? P32 : 0));   // HP_X1
    }
}

// ------------------------- small helpers ----------------------------------
__device__ __forceinline__ uint32_t smem_u32(const void* p){
    uint32_t a;
    asm("{ .reg .u64 t; cvta.to.shared.u64 t, %1; cvt.u32.u64 %0, t; }" : "=r"(a) : "l"(p));
    return a;
}
__device__ __forceinline__ void split_f32(float v, __half& hi, __half& lo){
    hi = __float2half_rn(v);
    lo = __float2half_rn(v - __half2float(hi));
}
__device__ __forceinline__ void cp16(uint32_t dst, const void* src){
    asm volatile("cp.async.cg.shared.global [%0], [%1], 16;" :: "r"(dst), "l"(src));
}
#define CP_COMMIT() asm volatile("cp.async.commit_group;" ::: "memory")
// SW64 swizzle: bits [5:4] ^= bits [8:7]  -> conflict-free ldmatrix at 64B rows
__device__ __forceinline__ uint32_t sw64(uint32_t off){ return off ^ ((off >> 3) & 0x30); }
#define LDSM_X4(r0,r1,r2,r3,addr) \
    asm volatile("ldmatrix.sync.aligned.m8n8.x4.shared.b16 {%0,%1,%2,%3}, [%4];" \
        : "=r"(r0), "=r"(r1), "=r"(r2), "=r"(r3) : "r"(addr))
#define MMA16816(d, a, b0, b1) \
    asm volatile("mma.sync.aligned.m16n8k16.row.col.f32.f16.f16.f32 " \
        "{%0,%1,%2,%3}, {%4,%5,%6,%7}, {%8,%9}, {%0,%1,%2,%3};" \
        : "+f"((d)[0]), "+f"((d)[1]), "+f"((d)[2]), "+f"((d)[3]) \
        : "r"((a)[0]), "r"((a)[1]), "r"((a)[2]), "r"((a)[3]), "r"(b0), "r"(b1))

// ------------------------- prep kernels -----------------------------------
__global__ void concat_convert_k(const float* __restrict__ prior, const float* __restrict__ gen){
    int i = blockIdx.x * blockDim.x + threadIdx.x;
    if (i >= BB * CCH) return;
    int b = i / CCH, c = i % CCH;
    float v = (c < PPD) ? prior[(size_t)b * PPD + c] : gen[(size_t)b * GGD + (c - PPD)];
    __half hi, lo; split_f32(v, hi, lo);
    g_comb_h[i] = hi; g_comb_l[i] = lo;
}
__global__ void pers_convert_k(const float* __restrict__ pers){
    int i = blockIdx.x * blockDim.x + threadIdx.x;
    if (i >= BB * GGD) return;
    __half hi, lo; split_f32(pers[i], hi, lo);
    g_pers_h[i] = hi; g_pers_l[i] = lo;
}

// One fused kernel transposes+converts ALL six weights.
__global__ void transpose_all_k(const float* __restrict__ Wp0, const float* __restrict__ Wg0,
                                const float* __restrict__ Wt0, const float* __restrict__ Wp1,
                                const float* __restrict__ Wg1, const float* __restrict__ Wt1){
    __shared__ float tile[32][33];
    int t = blockIdx.z;
    int bid = blockIdx.x;
    const float* src; __half* dh; __half* dl; int Kd, Nd, idx;
    if      (bid < 384)  { src=Wp0; dh=g_wppn0_h; dl=g_wppn0_l; Kd=CCH; Nd=H0; idx=bid; }
    else if (bid < 640)  { src=Wg0; dh=g_wgt0_h;  dl=g_wgt0_l;  Kd=H0;  Nd=H0; idx=bid-384; }
    else if (bid < 896)  { src=Wt0; dh=g_wtw0_h;  dl=g_wtw0_l;  Kd=GGD; Nd=H0; idx=bid-640; }
    else if (bid < 1088) { src=Wp1; dh=g_wppn1_h; dl=g_wppn1_l; Kd=CCH; Nd=H1; idx=bid-896; }
    else if (bid < 1152) { src=Wg1; dh=g_wgt1_h;  dl=g_wgt1_l;  Kd=H1;  Nd=H1; idx=bid-1088; }
    else                 { src=Wt1; dh=g_wtw1_h;  dl=g_wtw1_l;  Kd=H0;  Nd=H1; idx=bid-1152; }
    int kt = Kd / 32;
    int k0 = (idx % kt) * 32, n0 = (idx / kt) * 32;
    src += (size_t)t * Kd * Nd;
    dh  += (size_t)t * Nd * Kd;
    dl  += (size_t)t * Nd * Kd;
    int x = threadIdx.x;
    for (int yy = threadIdx.y; yy < 32; yy += 8)
        tile[yy][x] = src[(size_t)(k0 + yy) * Nd + n0 + x];
    __syncthreads();
    for (int yy = threadIdx.y; yy < 32; yy += 8){
        float v = tile[x][yy];
        __half hi, lo; split_f32(v, hi, lo);
        size_t o = (size_t)(n0 + yy) * Kd + k0 + x;
        dh[o] = hi; dl[o] = lo;
    }
}

// ------------------------- fp16-split GEMM --------------------------------
// CTA 128x128, 8 warps (4M x 2N), warp tile 32x64. KC=32.
// 3-stage cp.async multistage, ONE __syncthreads per chunk, SW64-swizzled SMEM.
// THREE=1: D = Ah*Bh + Ah*Bl + Al*Bh ; THREE=0 (gates): D = Ah*Bh + Ah*Bl
// THREE is a TEMPLATE param: the 2-term variant drops the Al tile at compile
// time (no cp.async, no LDSM, no MMA, no predicates in the 3-term build).
#define ROWB 64
#define TILEB 8192
#define STG   32768
#define NSTAGE 3
#define SMEM_DYN (NSTAGE*STG)

template<int THREE>
__global__ void __launch_bounds__(256, 2) gemm_fp16s(
    int a_id, size_t a_tstr, int lda, int K,
    int b_id, const float* __restrict__ bias,
    int aux_id, int out_id, int Ntot, int epi)
{
    extern __shared__ char smem[];
    uint32_t sb = smem_u32(smem);
    int tid = threadIdx.x, wid = tid >> 5, lid = tid & 31;
    int warp_m = wid & 3, warp_n = wid >> 2;
    int t  = blockIdx.z;
    int m0 = blockIdx.x * 128;
    int n0 = blockIdx.y * 128;

    const __half* Ah = get_hbuf(a_id, 0) + (size_t)t * a_tstr + (size_t)m0 * lda;
    const __half* Al = get_hbuf(a_id, 1) + (size_t)t * a_tstr + (size_t)m0 * lda;
    const __half* Bh = get_hbuf(b_id, 0) + ((size_t)t * Ntot + n0) * K;
    const __half* Bl = get_hbuf(b_id, 1) + ((size_t)t * Ntot + n0) * K;

    float acc[2][8][4];
    #pragma unroll
    for (int mi = 0; mi < 2; mi++)
        #pragma unroll
        for (int ni = 0; ni < 8; ni++)
            #pragma unroll
            for (int j = 0; j < 4; j++) acc[mi][ni][j] = 0.f;

    int nk = K >> 5;

    // ---- lane-constant ldmatrix offsets (swizzled), hoisted ----
    int lq = lid >> 3, lr = lid & 7;
    uint32_t a_row = (uint32_t)(warp_m * 32 + ((lq & 1) << 3) + lr);
    uint32_t a_cb  = (uint32_t)((lq >> 1) << 4);
    uint32_t b_row = (uint32_t)(warp_n * 64 + ((lq >> 1) << 3) + lr);
    uint32_t b_cb  = (uint32_t)((lq & 1) << 4);
    uint32_t aoff[2][2], boff[4][2];
    #pragma unroll
    for (int mi = 0; mi < 2; mi++)
        #pragma unroll
        for (int s = 0; s < 2; s++)
            aoff[mi][s] = sw64((a_row + mi * 16) * ROWB + s * 32 + a_cb);
    #pragma unroll
    for (int p = 0; p < 4; p++)
        #pragma unroll
        for (int s = 0; s < 2; s++)
            boff[p][s] = sw64((b_row + p * 16) * ROWB + s * 32 + b_cb);

    // ---- loader: fixed tile per thread (64 threads per tile) ----
    int l_tile = tid >> 6;            // 0..3 : Ah, Al, Bh, Bl
    int l_rem  = tid & 63;
    const __half* l_src0 = (l_tile == 0) ? Ah : (l_tile == 1) ? Al : (l_tile == 2) ? Bh : Bl;
    int l_ld = (l_tile < 2) ? lda : K;
    uint32_t l_dstbase = sb + (uint32_t)l_tile * TILEB;
    bool l_active = THREE || (l_tile != 1);   // 2-term: Al tile threads idle

    auto load_chunk = [&](int kc, int stage_sel){
        uint32_t stg = (uint32_t)stage_sel * (uint32_t)STG;
        if (l_active){
            const __half* src = l_src0 + kc * 32;
            #pragma unroll
            for (int it = 0; it < 8; it++){
                int slot = it * 64 + l_rem;
                int row  = slot >> 2, c = slot & 3;
                cp16(l_dstbase + stg + sw64((uint32_t)(row * ROWB + c * 16)),
                     src + (size_t)row * l_ld + c * 8);
            }
        }
        CP_COMMIT();
    };

    load_chunk(0, 0);
    load_chunk(1, 1);

    int stage = 0;
    for (int kc = 0; kc < nk; kc++){
        if (kc + 1 < nk)
            asm volatile("cp.async.wait_group 1;" ::: "memory");
        else
            asm volatile("cp.async.wait_group 0;" ::: "memory");
        __syncthreads();
        // prefetch kc+2 into stage (kc+2)%3 — safe: all warps passed the barrier
        if (kc + 2 < nk)
            load_chunk(kc + 2, (stage + 2 >= NSTAGE) ? stage + 2 - NSTAGE : stage + 2);

        uint32_t stg_b = sb + (uint32_t)stage * STG;
        uint32_t sAh = stg_b;
        uint32_t sAl = stg_b + TILEB;
        uint32_t sBh = stg_b + 2 * TILEB;
        uint32_t sBl = stg_b + 3 * TILEB;

        #pragma unroll
        for (int s = 0; s < 2; s++){
            uint32_t ah[2][4], al[2][4];
            #pragma unroll
            for (int mi = 0; mi < 2; mi++){
                LDSM_X4(ah[mi][0], ah[mi][1], ah[mi][2], ah[mi][3], sAh + aoff[mi][s]);
                if (THREE){
                    LDSM_X4(al[mi][0], al[mi][1], al[mi][2], al[mi][3], sAl + aoff[mi][s]);
                }
            }
            #pragma unroll
            for (int p = 0; p < 4; p++){
                uint32_t bh0, bh1, bh2, bh3, bl0, bl1, bl2, bl3;
                LDSM_X4(bh0, bh1, bh2, bh3, sBh + boff[p][s]);
                LDSM_X4(bl0, bl1, bl2, bl3, sBl + boff[p][s]);
                #pragma unroll
                for (int mi = 0; mi < 2; mi++){
                    MMA16816(acc[mi][2*p],   ah[mi], bh0, bh1);
                    MMA16816(acc[mi][2*p],   ah[mi], bl0, bl1);
                    MMA16816(acc[mi][2*p+1], ah[mi], bh2, bh3);
                    MMA16816(acc[mi][2*p+1], ah[mi], bl2, bl3);
                    if (THREE){
                        MMA16816(acc[mi][2*p],   al[mi], bh0, bh1);
                        MMA16816(acc[mi][2*p+1], al[mi], bh2, bh3);
                    }
                }
            }
        }
        stage = (stage + 1 >= NSTAGE) ? 0 : stage + 1;
    }

    // ---------------- epilogue ----------------
    const float* biasp = bias + (size_t)t * Ntot;
    const __half* axh = nullptr; const __half* axl = nullptr;
    if (epi){
        axh = get_hbuf(aux_id, 0) + (size_t)t * BB * Ntot;
        axl = get_hbuf(aux_id, 1) + (size_t)t * BB * Ntot;
    }
    __half* oh = get_hbuf(out_id, 0) + (size_t)t * BB * Ntot;
    __half* ol = get_hbuf(out_id, 1) + (size_t)t * BB * Ntot;

    int g = lid >> 2, tig = lid & 3;
    #pragma unroll
    for (int mi = 0; mi < 2; mi++){
        #pragma unroll
        for (int ni = 0; ni < 8; ni++){
            int col = n0 + warp_n * 64 + ni * 8 + 2 * tig;
            float2 bv = *(const float2*)(biasp + col);
            int row0 = m0 + warp_m * 32 + mi * 16 + g;
            #pragma unroll
            for (int h = 0; h < 2; h++){
                int row = row0 + h * 8;
                size_t off = (size_t)row * Ntot + col;
                float v0 = acc[mi][ni][2*h]   + bv.x;
                float v1 = acc[mi][ni][2*h+1] + bv.y;
                float a0 = 0.f, a1 = 0.f;
                if (epi){
                    __half2 hv = *(const __half2*)(axh + off);
                    __half2 lv = *(const __half2*)(axl + off);
                    a0 = __half2float(hv.x) + __half2float(lv.x);
                    a1 = __half2float(hv.y) + __half2float(lv.y);
                }
                float r0, r1;
                if (epi == 0){
                    r0 = fmaxf(v0, 0.f); r1 = fmaxf(v1, 0.f);
                } else if (epi == 1){
                    r0 = a0 * (1.f / (1.f + __expf(-2.f * v0)));
                    r1 = a1 * (1.f / (1.f + __expf(-2.f * v1)));
                } else {
                    r0 = fmaxf(v0 * a0, 0.f); r1 = fmaxf(v1 * a1, 0.f);
                }
                __half h0v, l0v, h1v, l1v;
                split_f32(r0, h0v, l0v); split_f32(r1, h1v, l1v);
                *(__half2*)(oh + off) = __halves2half2(h0v, h1v);
                *(__half2*)(ol + off) = __halves2half2(l0v, l1v);
            }
        }
    }
}

// ------------------------- output layer -----------------------------------
__global__ void out_k(const float* __restrict__ W2, const float* __restrict__ b2,
                      float* __restrict__ out){
    int b = blockIdx.x;
    int wid = threadIdx.x >> 5, lid = threadIdx.x & 31;   // wid = task
    const __half* xh = get_hbuf(HP_X1, 0) + ((size_t)wid * BB + b) * H1;
    const __half* xl = get_hbuf(HP_X1, 1) + ((size_t)wid * BB + b) * H1;
    const float* wr = W2 + (size_t)wid * H1;
    float s = 0.f;
    #pragma unroll
    for (int j = 0; j < 8; j++){
        int i = lid + 32 * j;
        s += (__half2float(xh[i]) + __half2float(xl[i])) * wr[i];
    }
    #pragma unroll
    for (int o = 16; o > 0; o >>= 1)
        s += __shfl_down_sync(0xFFFFFFFFu, s, o);
    if (lid == 0) out[(size_t)b * TT + wid] = s + b2[wid];
}

// ------------------------- launch -----------------------------------------
extern "C" void kernel_launch(void* const* d_in, const int* in_sizes, int n_in,
                              void* d_out, int out_size) {
    const float* prior    = (const float*)d_in[0];
    const float* gen      = (const float*)d_in[1];
    const float* pers     = (const float*)d_in[2];
    const float* tower_W0 = (const float*)d_in[3];
    const float* tower_b0 = (const float*)d_in[4];
    const float* tower_W1 = (const float*)d_in[5];
    const float* tower_b1 = (const float*)d_in[6];
    const float* tower_W2 = (const float*)d_in[7];
    const float* tower_b2 = (const float*)d_in[8];
    const float* ppn0_W   = (const float*)d_in[9];
    const float* ppn0_b   = (const float*)d_in[10];
    const float* gate0_W  = (const float*)d_in[11];
    const float* gate0_b  = (const float*)d_in[12];
    const float* ppn1_W   = (const float*)d_in[13];
    const float* ppn1_b   = (const float*)d_in[14];
    const float* gate1_W  = (const float*)d_in[15];
    const float* gate1_b  = (const float*)d_in[16];

    cudaFuncSetAttribute(gemm_fp16s<1>,
                         cudaFuncAttributeMaxDynamicSharedMemorySize, SMEM_DYN);
    cudaFuncSetAttribute(gemm_fp16s<0>,
                         cudaFuncAttributeMaxDynamicSharedMemorySize, SMEM_DYN);

    // launches 0,1,2: prep — launch index 5 (ncu -s 5 -c 1) is tower0 GEMM
    concat_convert_k<<<(BB * CCH) / 256, 256>>>(prior, gen);
    pers_convert_k<<<(BB * GGD) / 256, 256>>>(pers);
    transpose_all_k<<<dim3(1280, 1, TT), dim3(32, 8)>>>(
        ppn0_W, gate0_W, tower_W0, ppn1_W, gate1_W, tower_W1);

    // ppn0: h0 = relu(comb @ W + b)                 [K=768, N=512]   3-term
    gemm_fp16s<1><<<dim3(BB/128, H0/128, TT), 256, SMEM_DYN>>>(
        HP_COMB, 0, CCH, CCH, HP_WPPN0, ppn0_b, 0, HP_H0, H0, 0);
    // gate0: g0 = h0 * sigmoid(2*(h0 @ Wg + b))     [K=512, N=512]   2-term (damped)
    gemm_fp16s<0><<<dim3(BB/128, H0/128, TT), 256, SMEM_DYN>>>(
        HP_H0, (size_t)BB*H0, H0, H0, HP_WGT0, gate0_b, HP_H0, HP_G0, H0, 1);
    // tower0: x0 = relu((pers @ W0 + b0) * g0)      [K=512, N=512]   3-term (profiled)
    gemm_fp16s<1><<<dim3(BB/128, H0/128, TT), 256, SMEM_DYN>>>(
        HP_PERS, 0, GGD, GGD, HP_WTW0, tower_b0, HP_G0, HP_X0, H0, 2);
    // ppn1: h1 = relu(comb @ W + b)                 [K=768, N=256]   3-term
    gemm_fp16s<1><<<dim3(BB/128, H1/128, TT), 256, SMEM_DYN>>>(
        HP_COMB, 0, CCH, CCH, HP_WPPN1, ppn1_b, 0, HP_H1, H1, 0);
    // gate1: g1 = h1 * sigmoid(2*(h1 @ Wg + b))     [K=256, N=256]   2-term (damped)
    gemm_fp16s<0><<<dim3(BB/128, H1/128, TT), 256, SMEM_DYN>>>(
        HP_H1, (size_t)BB*H1, H1, H1, HP_WGT1, gate1_b, HP_H1, HP_G1, H1, 1);
    // tower1: x1 = relu((x0 @ W1 + b1) * g1)        [K=512, N=256]   3-term
    gemm_fp16s<1><<<dim3(BB/128, H1/128, TT), 256, SMEM_DYN>>>(
        HP_X0, (size_t)BB*H0, H0, H0, HP_WTW1, tower_b1, HP_G1, HP_X1, H1, 2);

    out_k<<<BB, 256>>>(tower_W2, tower_b2, (float*)d_out);
}

// round 12
// speedup vs baseline: 1.9526x; 1.2802x over previous
#include <cuda_runtime.h>
#include <cuda_fp16.h>
#include <cstdint>
#include <cstddef>

#define BB  8192
#define TT  8
#define PPD 256
#define GGD 512
#define CCH 768
#define H0  512
#define H1  256

// ------------------------- device scratch (352 MB total) -------------------
__device__ __align__(256) __half g_comb_h [(size_t)BB*CCH];
__device__ __align__(256) __half g_comb_l [(size_t)BB*CCH];
__device__ __align__(256) __half g_pers_h [(size_t)BB*GGD];
__device__ __align__(256) __half g_pers_l [(size_t)BB*GGD];
__device__ __align__(256) __half g_wppn0_h[(size_t)TT*H0*CCH];
__device__ __align__(256) __half g_wppn0_l[(size_t)TT*H0*CCH];
__device__ __align__(256) __half g_wgt0_h [(size_t)TT*H0*H0];
__device__ __align__(256) __half g_wgt0_l [(size_t)TT*H0*H0];
__device__ __align__(256) __half g_wtw0_h [(size_t)TT*H0*GGD];
__device__ __align__(256) __half g_wtw0_l [(size_t)TT*H0*GGD];
__device__ __align__(256) __half g_wppn1_h[(size_t)TT*H1*CCH];
__device__ __align__(256) __half g_wppn1_l[(size_t)TT*H1*CCH];
__device__ __align__(256) __half g_wgt1_h [(size_t)TT*H1*H1];
__device__ __align__(256) __half g_wgt1_l [(size_t)TT*H1*H1];
__device__ __align__(256) __half g_wtw1_h [(size_t)TT*H1*H0];
__device__ __align__(256) __half g_wtw1_l [(size_t)TT*H1*H0];

// Aliased activation pools (stream order makes every overwrite safe; see R5/R6)
#define P64  67108864ull
#define P32  33554432ull
__device__ __align__(256) unsigned char g_poolA[2ull*P64];
__device__ __align__(256) unsigned char g_poolB[2ull*P64];

enum { HP_COMB=0, HP_PERS, HP_WPPN0, HP_WGT0, HP_WTW0, HP_WPPN1, HP_WGT1, HP_WTW1,
       HP_H0, HP_X0, HP_G0, HP_H1, HP_G1, HP_X1 };

__device__ __forceinline__ __half* get_hbuf(int id, int plane){
    switch(id){
        case HP_COMB:  return plane ? g_comb_l  : g_comb_h;
        case HP_PERS:  return plane ? g_pers_l  : g_pers_h;
        case HP_WPPN0: return plane ? g_wppn0_l : g_wppn0_h;
        case HP_WGT0:  return plane ? g_wgt0_l  : g_wgt0_h;
        case HP_WTW0:  return plane ? g_wtw0_l  : g_wtw0_h;
        case HP_WPPN1: return plane ? g_wppn1_l : g_wppn1_h;
        case HP_WGT1:  return plane ? g_wgt1_l  : g_wgt1_h;
        case HP_WTW1:  return plane ? g_wtw1_l  : g_wtw1_h;
        case HP_H0:    return (__half*)(g_poolA + (plane ? P64 : 0));
        case HP_X0:    return (__half*)(g_poolA + (plane ? P64 : 0));
        case HP_G0:    return (__half*)(g_poolB + (plane ? P64 : 0));
        case HP_H1:    return (__half*)(g_poolB + (plane ? P32 : 0));
        case HP_G1:    return (__half*)(g_poolB + P64 + (plane ? P32 : 0));
        default:       return (__half*)(g_poolB + (plane ? P32 : 0));   // HP_X1
    }
}

// ------------------------- small helpers ----------------------------------
__device__ __forceinline__ uint32_t smem_u32(const void* p){
    uint32_t a;
    asm("{ .reg .u64 t; cvta.to.shared.u64 t, %1; cvt.u32.u64 %0, t; }" : "=r"(a) : "l"(p));
    return a;
}
__device__ __forceinline__ void split_f32(float v, __half& hi, __half& lo){
    hi = __float2half_rn(v);
    lo = __float2half_rn(v - __half2float(hi));
}
__device__ __forceinline__ void cp16(uint32_t dst, const void* src){
    asm volatile("cp.async.cg.shared.global [%0], [%1], 16;" :: "r"(dst), "l"(src));
}
#define CP_COMMIT() asm volatile("cp.async.commit_group;" ::: "memory")
// SW64 swizzle: bits [5:4] ^= bits [8:7]  -> conflict-free ldmatrix at 64B rows
__device__ __forceinline__ uint32_t sw64(uint32_t off){ return off ^ ((off >> 3) & 0x30); }
#define LDSM_X4(r0,r1,r2,r3,addr) \
    asm volatile("ldmatrix.sync.aligned.m8n8.x4.shared.b16 {%0,%1,%2,%3}, [%4];" \
        : "=r"(r0), "=r"(r1), "=r"(r2), "=r"(r3) : "r"(addr))
#define MMA16816(d, a, b0, b1) \
    asm volatile("mma.sync.aligned.m16n8k16.row.col.f32.f16.f16.f32 " \
        "{%0,%1,%2,%3}, {%4,%5,%6,%7}, {%8,%9}, {%0,%1,%2,%3};" \
        : "+f"((d)[0]), "+f"((d)[1]), "+f"((d)[2]), "+f"((d)[3]) \
        : "r"((a)[0]), "r"((a)[1]), "r"((a)[2]), "r"((a)[3]), "r"(b0), "r"(b1))

// ------------------------- prep kernels -----------------------------------
__global__ void concat_convert_k(const float* __restrict__ prior, const float* __restrict__ gen){
    int i = blockIdx.x * blockDim.x + threadIdx.x;
    if (i >= BB * CCH) return;
    int b = i / CCH, c = i % CCH;
    float v = (c < PPD) ? prior[(size_t)b * PPD + c] : gen[(size_t)b * GGD + (c - PPD)];
    __half hi, lo; split_f32(v, hi, lo);
    g_comb_h[i] = hi; g_comb_l[i] = lo;
}
__global__ void pers_convert_k(const float* __restrict__ pers){
    int i = blockIdx.x * blockDim.x + threadIdx.x;
    if (i >= BB * GGD) return;
    __half hi, lo; split_f32(pers[i], hi, lo);
    g_pers_h[i] = hi; g_pers_l[i] = lo;
}

// One fused kernel transposes+converts ALL six weights.
__global__ void transpose_all_k(const float* __restrict__ Wp0, const float* __restrict__ Wg0,
                                const float* __restrict__ Wt0, const float* __restrict__ Wp1,
                                const float* __restrict__ Wg1, const float* __restrict__ Wt1){
    __shared__ float tile[32][33];
    int t = blockIdx.z;
    int bid = blockIdx.x;
    const float* src; __half* dh; __half* dl; int Kd, Nd, idx;
    if      (bid < 384)  { src=Wp0; dh=g_wppn0_h; dl=g_wppn0_l; Kd=CCH; Nd=H0; idx=bid; }
    else if (bid < 640)  { src=Wg0; dh=g_wgt0_h;  dl=g_wgt0_l;  Kd=H0;  Nd=H0; idx=bid-384; }
    else if (bid < 896)  { src=Wt0; dh=g_wtw0_h;  dl=g_wtw0_l;  Kd=GGD; Nd=H0; idx=bid-640; }
    else if (bid < 1088) { src=Wp1; dh=g_wppn1_h; dl=g_wppn1_l; Kd=CCH; Nd=H1; idx=bid-896; }
    else if (bid < 1152) { src=Wg1; dh=g_wgt1_h;  dl=g_wgt1_l;  Kd=H1;  Nd=H1; idx=bid-1088; }
    else                 { src=Wt1; dh=g_wtw1_h;  dl=g_wtw1_l;  Kd=H0;  Nd=H1; idx=bid-1152; }
    int kt = Kd / 32;
    int k0 = (idx % kt) * 32, n0 = (idx / kt) * 32;
    src += (size_t)t * Kd * Nd;
    dh  += (size_t)t * Nd * Kd;
    dl  += (size_t)t * Nd * Kd;
    int x = threadIdx.x;
    for (int yy = threadIdx.y; yy < 32; yy += 8)
        tile[yy][x] = src[(size_t)(k0 + yy) * Nd + n0 + x];
    __syncthreads();
    for (int yy = threadIdx.y; yy < 32; yy += 8){
        float v = tile[x][yy];
        __half hi, lo; split_f32(v, hi, lo);
        size_t o = (size_t)(n0 + yy) * Kd + k0 + x;
        dh[o] = hi; dl[o] = lo;
    }
}

// ------------------------- fp16-split GEMM --------------------------------
// CTA 128x128, 8 warps (4M x 2N), warp tile 32x64. KC=32.
// 3-stage cp.async multistage, ONE __syncthreads per chunk, SW64-swizzled SMEM.
// THREE=1: D = Ah*Bh + Ah*Bl + Al*Bh ; THREE=0: D = Ah*Bh + Ah*Bl
// 2-term error is calibrated at ~1-2e-4/GEMM (R10/R11 measurements); all-2-term
// predicted total ~5e-4 < 1e-3 gate. wlo=0 skips the lo-plane output store
// (used for x0, whose lo plane has no consumer once tower1 is 2-term).
#define ROWB 64
#define TILEB 8192
#define STG   32768
#define NSTAGE 3
#define SMEM_DYN (NSTAGE*STG)

template<int THREE>
__global__ void __launch_bounds__(256, 2) gemm_fp16s(
    int a_id, size_t a_tstr, int lda, int K,
    int b_id, const float* __restrict__ bias,
    int aux_id, int out_id, int Ntot, int epi, int wlo)
{
    extern __shared__ char smem[];
    uint32_t sb = smem_u32(smem);
    int tid = threadIdx.x, wid = tid >> 5, lid = tid & 31;
    int warp_m = wid & 3, warp_n = wid >> 2;
    int t  = blockIdx.z;
    int m0 = blockIdx.x * 128;
    int n0 = blockIdx.y * 128;

    const __half* Ah = get_hbuf(a_id, 0) + (size_t)t * a_tstr + (size_t)m0 * lda;
    const __half* Al = get_hbuf(a_id, 1) + (size_t)t * a_tstr + (size_t)m0 * lda;
    const __half* Bh = get_hbuf(b_id, 0) + ((size_t)t * Ntot + n0) * K;
    const __half* Bl = get_hbuf(b_id, 1) + ((size_t)t * Ntot + n0) * K;

    float acc[2][8][4];
    #pragma unroll
    for (int mi = 0; mi < 2; mi++)
        #pragma unroll
        for (int ni = 0; ni < 8; ni++)
            #pragma unroll
            for (int j = 0; j < 4; j++) acc[mi][ni][j] = 0.f;

    int nk = K >> 5;

    // ---- lane-constant ldmatrix offsets (swizzled), hoisted ----
    int lq = lid >> 3, lr = lid & 7;
    uint32_t a_row = (uint32_t)(warp_m * 32 + ((lq & 1) << 3) + lr);
    uint32_t a_cb  = (uint32_t)((lq >> 1) << 4);
    uint32_t b_row = (uint32_t)(warp_n * 64 + ((lq >> 1) << 3) + lr);
    uint32_t b_cb  = (uint32_t)((lq & 1) << 4);
    uint32_t aoff[2][2], boff[4][2];
    #pragma unroll
    for (int mi = 0; mi < 2; mi++)
        #pragma unroll
        for (int s = 0; s < 2; s++)
            aoff[mi][s] = sw64((a_row + mi * 16) * ROWB + s * 32 + a_cb);
    #pragma unroll
    for (int p = 0; p < 4; p++)
        #pragma unroll
        for (int s = 0; s < 2; s++)
            boff[p][s] = sw64((b_row + p * 16) * ROWB + s * 32 + b_cb);

    // ---- loaders (compile-time selected) ----
    // THREE=1: 4 tiles (Ah,Al,Bh,Bl), 64 threads each, 8 slots/thread.
    // THREE=0: 3 tiles (Ah,Bh,Bl), ALL 256 threads, 2 slots per tile per thread.
    int l_tile = tid >> 6;            // THREE=1 path
    int l_rem  = tid & 63;
    const __half* l_src0 = (l_tile == 0) ? Ah : (l_tile == 1) ? Al : (l_tile == 2) ? Bh : Bl;
    int l_ld = (l_tile < 2) ? lda : K;
    uint32_t l_dstbase = sb + (uint32_t)l_tile * TILEB;

    // THREE=0 path: thread-constant rows/cols + swizzled dst offsets
    int c3   = tid & 3;
    int row3a = tid >> 2;            // 0..63
    int row3b = row3a + 64;          // 64..127
    uint32_t d3a = sw64((uint32_t)(row3a * ROWB + c3 * 16));
    uint32_t d3b = sw64((uint32_t)(row3b * ROWB + c3 * 16));

    auto load_chunk = [&](int kc, int stage_sel){
        uint32_t stg = (uint32_t)stage_sel * (uint32_t)STG;
        if (THREE){
            const __half* src = l_src0 + kc * 32;
            #pragma unroll
            for (int it = 0; it < 8; it++){
                int slot = it * 64 + l_rem;
                int row  = slot >> 2, c = slot & 3;
                cp16(l_dstbase + stg + sw64((uint32_t)(row * ROWB + c * 16)),
                     src + (size_t)row * l_ld + c * 8);
            }
        } else {
            const __half* sA = Ah + kc * 32;
            const __half* sH = Bh + kc * 32;
            const __half* sL = Bl + kc * 32;
            uint32_t baseA = sb + stg;                 // tile slot 0 (sAh)
            uint32_t baseH = sb + stg + 2u * TILEB;    // tile slot 2 (sBh)
            uint32_t baseL = sb + stg + 3u * TILEB;    // tile slot 3 (sBl)
            cp16(baseA + d3a, sA + (size_t)row3a * lda + c3 * 8);
            cp16(baseA + d3b, sA + (size_t)row3b * lda + c3 * 8);
            cp16(baseH + d3a, sH + (size_t)row3a * K   + c3 * 8);
            cp16(baseH + d3b, sH + (size_t)row3b * K   + c3 * 8);
            cp16(baseL + d3a, sL + (size_t)row3a * K   + c3 * 8);
            cp16(baseL + d3b, sL + (size_t)row3b * K   + c3 * 8);
        }
        CP_COMMIT();
    };

    load_chunk(0, 0);
    load_chunk(1, 1);

    int stage = 0;
    for (int kc = 0; kc < nk; kc++){
        if (kc + 1 < nk)
            asm volatile("cp.async.wait_group 1;" ::: "memory");
        else
            asm volatile("cp.async.wait_group 0;" ::: "memory");
        __syncthreads();
        // prefetch kc+2 into stage (kc+2)%3 — safe: all warps passed the barrier
        if (kc + 2 < nk)
            load_chunk(kc + 2, (stage + 2 >= NSTAGE) ? stage + 2 - NSTAGE : stage + 2);

        uint32_t stg_b = sb + (uint32_t)stage * STG;
        uint32_t sAh = stg_b;
        uint32_t sAl = stg_b + TILEB;
        uint32_t sBh = stg_b + 2 * TILEB;
        uint32_t sBl = stg_b + 3 * TILEB;

        #pragma unroll
        for (int s = 0; s < 2; s++){
            uint32_t ah[2][4], al[2][4];
            #pragma unroll
            for (int mi = 0; mi < 2; mi++){
                LDSM_X4(ah[mi][0], ah[mi][1], ah[mi][2], ah[mi][3], sAh + aoff[mi][s]);
                if (THREE){
                    LDSM_X4(al[mi][0], al[mi][1], al[mi][2], al[mi][3], sAl + aoff[mi][s]);
                }
            }
            #pragma unroll
            for (int p = 0; p < 4; p++){
                uint32_t bh0, bh1, bh2, bh3, bl0, bl1, bl2, bl3;
                LDSM_X4(bh0, bh1, bh2, bh3, sBh + boff[p][s]);
                LDSM_X4(bl0, bl1, bl2, bl3, sBl + boff[p][s]);
                #pragma unroll
                for (int mi = 0; mi < 2; mi++){
                    MMA16816(acc[mi][2*p],   ah[mi], bh0, bh1);
                    MMA16816(acc[mi][2*p],   ah[mi], bl0, bl1);
                    MMA16816(acc[mi][2*p+1], ah[mi], bh2, bh3);
                    MMA16816(acc[mi][2*p+1], ah[mi], bl2, bl3);
                    if (THREE){
                        MMA16816(acc[mi][2*p],   al[mi], bh0, bh1);
                        MMA16816(acc[mi][2*p+1], al[mi], bh2, bh3);
                    }
                }
            }
        }
        stage = (stage + 1 >= NSTAGE) ? 0 : stage + 1;
    }

    // ---------------- epilogue ----------------
    const float* biasp = bias + (size_t)t * Ntot;
    const __half* axh = nullptr; const __half* axl = nullptr;
    if (epi){
        axh = get_hbuf(aux_id, 0) + (size_t)t * BB * Ntot;
        axl = get_hbuf(aux_id, 1) + (size_t)t * BB * Ntot;
    }
    __half* oh = get_hbuf(out_id, 0) + (size_t)t * BB * Ntot;
    __half* ol = get_hbuf(out_id, 1) + (size_t)t * BB * Ntot;

    int g = lid >> 2, tig = lid & 3;
    #pragma unroll
    for (int mi = 0; mi < 2; mi++){
        #pragma unroll
        for (int ni = 0; ni < 8; ni++){
            int col = n0 + warp_n * 64 + ni * 8 + 2 * tig;
            float2 bv = *(const float2*)(biasp + col);
            int row0 = m0 + warp_m * 32 + mi * 16 + g;
            #pragma unroll
            for (int h = 0; h < 2; h++){
                int row = row0 + h * 8;
                size_t off = (size_t)row * Ntot + col;
                float v0 = acc[mi][ni][2*h]   + bv.x;
                float v1 = acc[mi][ni][2*h+1] + bv.y;
                float a0 = 0.f, a1 = 0.f;
                if (epi){
                    __half2 hv = *(const __half2*)(axh + off);
                    __half2 lv = *(const __half2*)(axl + off);
                    a0 = __half2float(hv.x) + __half2float(lv.x);
                    a1 = __half2float(hv.y) + __half2float(lv.y);
                }
                float r0, r1;
                if (epi == 0){
                    r0 = fmaxf(v0, 0.f); r1 = fmaxf(v1, 0.f);
                } else if (epi == 1){
                    r0 = a0 * (1.f / (1.f + __expf(-2.f * v0)));
                    r1 = a1 * (1.f / (1.f + __expf(-2.f * v1)));
                } else {
                    r0 = fmaxf(v0 * a0, 0.f); r1 = fmaxf(v1 * a1, 0.f);
                }
                __half h0v, l0v, h1v, l1v;
                split_f32(r0, h0v, l0v); split_f32(r1, h1v, l1v);
                *(__half2*)(oh + off) = __halves2half2(h0v, h1v);
                if (wlo)
                    *(__half2*)(ol + off) = __halves2half2(l0v, l1v);
            }
        }
    }
}

// ------------------------- output layer -----------------------------------
__global__ void out_k(const float* __restrict__ W2, const float* __restrict__ b2,
                      float* __restrict__ out){
    int b = blockIdx.x;
    int wid = threadIdx.x >> 5, lid = threadIdx.x & 31;   // wid = task
    const __half* xh = get_hbuf(HP_X1, 0) + ((size_t)wid * BB + b) * H1;
    const __half* xl = get_hbuf(HP_X1, 1) + ((size_t)wid * BB + b) * H1;
    const float* wr = W2 + (size_t)wid * H1;
    float s = 0.f;
    #pragma unroll
    for (int j = 0; j < 8; j++){
        int i = lid + 32 * j;
        s += (__half2float(xh[i]) + __half2float(xl[i])) * wr[i];
    }
    #pragma unroll
    for (int o = 16; o > 0; o >>= 1)
        s += __shfl_down_sync(0xFFFFFFFFu, s, o);
    if (lid == 0) out[(size_t)b * TT + wid] = s + b2[wid];
}

// ------------------------- launch -----------------------------------------
extern "C" void kernel_launch(void* const* d_in, const int* in_sizes, int n_in,
                              void* d_out, int out_size) {
    const float* prior    = (const float*)d_in[0];
    const float* gen      = (const float*)d_in[1];
    const float* pers     = (const float*)d_in[2];
    const float* tower_W0 = (const float*)d_in[3];
    const float* tower_b0 = (const float*)d_in[4];
    const float* tower_W1 = (const float*)d_in[5];
    const float* tower_b1 = (const float*)d_in[6];
    const float* tower_W2 = (const float*)d_in[7];
    const float* tower_b2 = (const float*)d_in[8];
    const float* ppn0_W   = (const float*)d_in[9];
    const float* ppn0_b   = (const float*)d_in[10];
    const float* gate0_W  = (const float*)d_in[11];
    const float* gate0_b  = (const float*)d_in[12];
    const float* ppn1_W   = (const float*)d_in[13];
    const float* ppn1_b   = (const float*)d_in[14];
    const float* gate1_W  = (const float*)d_in[15];
    const float* gate1_b  = (const float*)d_in[16];

    cudaFuncSetAttribute(gemm_fp16s<0>,
                         cudaFuncAttributeMaxDynamicSharedMemorySize, SMEM_DYN);

    // launches 0,1,2: prep — launch index 5 (ncu -s 5 -c 1) is tower0 GEMM
    concat_convert_k<<<(BB * CCH) / 256, 256>>>(prior, gen);
    pers_convert_k<<<(BB * GGD) / 256, 256>>>(pers);
    transpose_all_k<<<dim3(1280, 1, TT), dim3(32, 8)>>>(
        ppn0_W, gate0_W, tower_W0, ppn1_W, gate1_W, tower_W1);

    // ppn0: h0 = relu(comb @ W + b)                 [K=768, N=512]
    gemm_fp16s<0><<<dim3(BB/128, H0/128, TT), 256, SMEM_DYN>>>(
        HP_COMB, 0, CCH, CCH, HP_WPPN0, ppn0_b, 0, HP_H0, H0, 0, 1);
    // gate0: g0 = h0 * sigmoid(2*(h0 @ Wg + b))     [K=512, N=512]
    gemm_fp16s<0><<<dim3(BB/128, H0/128, TT), 256, SMEM_DYN>>>(
        HP_H0, (size_t)BB*H0, H0, H0, HP_WGT0, gate0_b, HP_H0, HP_G0, H0, 1, 1);
    // tower0: x0 = relu((pers @ W0 + b0) * g0)      [K=512, N=512]   (profiled; x0 lo dead)
    gemm_fp16s<0><<<dim3(BB/128, H0/128, TT), 256, SMEM_DYN>>>(
        HP_PERS, 0, GGD, GGD, HP_WTW0, tower_b0, HP_G0, HP_X0, H0, 2, 0);
    // ppn1: h1 = relu(comb @ W + b)                 [K=768, N=256]
    gemm_fp16s<0><<<dim3(BB/128, H1/128, TT), 256, SMEM_DYN>>>(
        HP_COMB, 0, CCH, CCH, HP_WPPN1, ppn1_b, 0, HP_H1, H1, 0, 1);
    // gate1: g1 = h1 * sigmoid(2*(h1 @ Wg + b))     [K=256, N=256]
    gemm_fp16s<0><<<dim3(BB/128, H1/128, TT), 256, SMEM_DYN>>>(
        HP_H1, (size_t)BB*H1, H1, H1, HP_WGT1, gate1_b, HP_H1, HP_G1, H1, 1, 1);
    // tower1: x1 = relu((x0 @ W1 + b1) * g1)        [K=512, N=256]   (exact: x0 is fp16)
    gemm_fp16s<0><<<dim3(BB/128, H1/128, TT), 256, SMEM_DYN>>>(
        HP_X0, (size_t)BB*H0, H0, H0, HP_WTW1, tower_b1, HP_G1, HP_X1, H1, 2, 1);

    out_k<<<BB, 256>>>(tower_W2, tower_b2, (float*)d_out);
}

// round 13
// speedup vs baseline: 2.0932x; 1.0720x over previous
#include <cuda_runtime.h>
#include <cuda_fp16.h>
#include <cstdint>
#include <cstddef>

#define BB  8192
#define TT  8
#define PPD 256
#define GGD 512
#define CCH 768
#define H0  512
#define H1  256

// ------------------------- device scratch (352 MB total) -------------------
__device__ __align__(256) __half g_comb_h [(size_t)BB*CCH];
__device__ __align__(256) __half g_comb_l [(size_t)BB*CCH];
__device__ __align__(256) __half g_pers_h [(size_t)BB*GGD];
__device__ __align__(256) __half g_pers_l [(size_t)BB*GGD];
__device__ __align__(256) __half g_wppn0_h[(size_t)TT*H0*CCH];
__device__ __align__(256) __half g_wppn0_l[(size_t)TT*H0*CCH];
__device__ __align__(256) __half g_wgt0_h [(size_t)TT*H0*H0];
__device__ __align__(256) __half g_wgt0_l [(size_t)TT*H0*H0];
__device__ __align__(256) __half g_wtw0_h [(size_t)TT*H0*GGD];
__device__ __align__(256) __half g_wtw0_l [(size_t)TT*H0*GGD];
__device__ __align__(256) __half g_wppn1_h[(size_t)TT*H1*CCH];
__device__ __align__(256) __half g_wppn1_l[(size_t)TT*H1*CCH];
__device__ __align__(256) __half g_wgt1_h [(size_t)TT*H1*H1];
__device__ __align__(256) __half g_wgt1_l [(size_t)TT*H1*H1];
__device__ __align__(256) __half g_wtw1_h [(size_t)TT*H1*H0];
__device__ __align__(256) __half g_wtw1_l [(size_t)TT*H1*H0];

// Aliased activation pools (stream order makes every overwrite safe; see R5/R6)
#define P64  67108864ull
#define P32  33554432ull
__device__ __align__(256) unsigned char g_poolA[2ull*P64];
__device__ __align__(256) unsigned char g_poolB[2ull*P64];

enum { HP_COMB=0, HP_PERS, HP_WPPN0, HP_WGT0, HP_WTW0, HP_WPPN1, HP_WGT1, HP_WTW1,
       HP_H0, HP_X0, HP_G0, HP_H1, HP_G1, HP_X1 };

__device__ __forceinline__ __half* get_hbuf(int id, int plane){
    switch(id){
        case HP_COMB:  return plane ? g_comb_l  : g_comb_h;
        case HP_PERS:  return plane ? g_pers_l  : g_pers_h;
        case HP_WPPN0: return plane ? g_wppn0_l : g_wppn0_h;
        case HP_WGT0:  return plane ? g_wgt0_l  : g_wgt0_h;
        case HP_WTW0:  return plane ? g_wtw0_l  : g_wtw0_h;
        case HP_WPPN1: return plane ? g_wppn1_l : g_wppn1_h;
        case HP_WGT1:  return plane ? g_wgt1_l  : g_wgt1_h;
        case HP_WTW1:  return plane ? g_wtw1_l  : g_wtw1_h;
        case HP_H0:    return (__half*)(g_poolA + (plane ? P64 : 0));
        case HP_X0:    return (__half*)(g_poolA + (plane ? P64 : 0));
        case HP_G0:    return (__half*)(g_poolB + (plane ? P64 : 0));
        case HP_H1:    return (__half*)(g_poolB + (plane ? P32 : 0));
        case HP_G1:    return (__half*)(g_poolB + P64 + (plane ? P32 : 0));
        default:       return (__half*)(g_poolB + (plane ? P32 : 0));   // HP_X1
    }
}

// ------------------------- small helpers ----------------------------------
__device__ __forceinline__ uint32_t smem_u32(const void* p){
    uint32_t a;
    asm("{ .reg .u64 t; cvta.to.shared.u64 t, %1; cvt.u32.u64 %0, t; }" : "=r"(a) : "l"(p));
    return a;
}
__device__ __forceinline__ void split_f32(float v, __half& hi, __half& lo){
    hi = __float2half_rn(v);
    lo = __float2half_rn(v - __half2float(hi));
}
__device__ __forceinline__ void cp16(uint32_t dst, const void* src){
    asm volatile("cp.async.cg.shared.global [%0], [%1], 16;" :: "r"(dst), "l"(src));
}
#define CP_COMMIT() asm volatile("cp.async.commit_group;" ::: "memory")
// SW128 swizzle: bits [6:4] ^= bits [9:7] — conflict-free ldmatrix at 128B rows
__device__ __forceinline__ uint32_t sw128(uint32_t off){ return off ^ ((off >> 3) & 0x70); }
#define LDSM_X4(r0,r1,r2,r3,addr) \
    asm volatile("ldmatrix.sync.aligned.m8n8.x4.shared.b16 {%0,%1,%2,%3}, [%4];" \
        : "=r"(r0), "=r"(r1), "=r"(r2), "=r"(r3) : "r"(addr))
#define MMA16816(d, a, b0, b1) \
    asm volatile("mma.sync.aligned.m16n8k16.row.col.f32.f16.f16.f32 " \
        "{%0,%1,%2,%3}, {%4,%5,%6,%7}, {%8,%9}, {%0,%1,%2,%3};" \
        : "+f"((d)[0]), "+f"((d)[1]), "+f"((d)[2]), "+f"((d)[3]) \
        : "r"((a)[0]), "r"((a)[1]), "r"((a)[2]), "r"((a)[3]), "r"(b0), "r"(b1))

// ------------------------- prep kernels -----------------------------------
__global__ void concat_convert_k(const float* __restrict__ prior, const float* __restrict__ gen){
    int i = blockIdx.x * blockDim.x + threadIdx.x;
    if (i >= BB * CCH) return;
    int b = i / CCH, c = i % CCH;
    float v = (c < PPD) ? prior[(size_t)b * PPD + c] : gen[(size_t)b * GGD + (c - PPD)];
    __half hi, lo; split_f32(v, hi, lo);
    g_comb_h[i] = hi; g_comb_l[i] = lo;
}
__global__ void pers_convert_k(const float* __restrict__ pers){
    int i = blockIdx.x * blockDim.x + threadIdx.x;
    if (i >= BB * GGD) return;
    __half hi, lo; split_f32(pers[i], hi, lo);
    g_pers_h[i] = hi; g_pers_l[i] = lo;
}

// One fused kernel transposes+converts ALL six weights.
__global__ void transpose_all_k(const float* __restrict__ Wp0, const float* __restrict__ Wg0,
                                const float* __restrict__ Wt0, const float* __restrict__ Wp1,
                                const float* __restrict__ Wg1, const float* __restrict__ Wt1){
    __shared__ float tile[32][33];
    int t = blockIdx.z;
    int bid = blockIdx.x;
    const float* src; __half* dh; __half* dl; int Kd, Nd, idx;
    if      (bid < 384)  { src=Wp0; dh=g_wppn0_h; dl=g_wppn0_l; Kd=CCH; Nd=H0; idx=bid; }
    else if (bid < 640)  { src=Wg0; dh=g_wgt0_h;  dl=g_wgt0_l;  Kd=H0;  Nd=H0; idx=bid-384; }
    else if (bid < 896)  { src=Wt0; dh=g_wtw0_h;  dl=g_wtw0_l;  Kd=GGD; Nd=H0; idx=bid-640; }
    else if (bid < 1088) { src=Wp1; dh=g_wppn1_h; dl=g_wppn1_l; Kd=CCH; Nd=H1; idx=bid-896; }
    else if (bid < 1152) { src=Wg1; dh=g_wgt1_h;  dl=g_wgt1_l;  Kd=H1;  Nd=H1; idx=bid-1088; }
    else                 { src=Wt1; dh=g_wtw1_h;  dl=g_wtw1_l;  Kd=H0;  Nd=H1; idx=bid-1152; }
    int kt = Kd / 32;
    int k0 = (idx % kt) * 32, n0 = (idx / kt) * 32;
    src += (size_t)t * Kd * Nd;
    dh  += (size_t)t * Nd * Kd;
    dl  += (size_t)t * Nd * Kd;
    int x = threadIdx.x;
    for (int yy = threadIdx.y; yy < 32; yy += 8)
        tile[yy][x] = src[(size_t)(k0 + yy) * Nd + n0 + x];
    __syncthreads();
    for (int yy = threadIdx.y; yy < 32; yy += 8){
        float v = tile[x][yy];
        __half hi, lo; split_f32(v, hi, lo);
        size_t o = (size_t)(n0 + yy) * Kd + k0 + x;
        dh[o] = hi; dl[o] = lo;
    }
}

// ------------------------- fp16-split 2-term GEMM --------------------------
// CTA 128x128, 8 warps (4M x 2N), warp tile 32x64. KC=64, 2-stage, SW128.
// D = A_hi*B_hi + A_hi*B_lo  (fp32 accumulate). Stage = 3 tiles (Ah,Bh,Bl) x 16KB.
// One __syncthreads per chunk; 4 k16-slices per chunk (2x fewer barriers than KC=32).
// wlo=0 skips the lo-plane output store (x0's lo plane has no consumer).
#define ROWB 128
#define TILEB 16384
#define STG   49152
#define SMEM_DYN (2*STG)

__global__ void __launch_bounds__(256, 2) gemm_fp16s(
    int a_id, size_t a_tstr, int lda, int K,
    int b_id, const float* __restrict__ bias,
    int aux_id, int out_id, int Ntot, int epi, int wlo)
{
    extern __shared__ char smem[];
    uint32_t sb = smem_u32(smem);
    int tid = threadIdx.x, wid = tid >> 5, lid = tid & 31;
    int warp_m = wid & 3, warp_n = wid >> 2;
    int t  = blockIdx.z;
    int m0 = blockIdx.x * 128;
    int n0 = blockIdx.y * 128;

    const __half* Ah = get_hbuf(a_id, 0) + (size_t)t * a_tstr + (size_t)m0 * lda;
    const __half* Bh = get_hbuf(b_id, 0) + ((size_t)t * Ntot + n0) * K;
    const __half* Bl = get_hbuf(b_id, 1) + ((size_t)t * Ntot + n0) * K;

    float acc[2][8][4];
    #pragma unroll
    for (int mi = 0; mi < 2; mi++)
        #pragma unroll
        for (int ni = 0; ni < 8; ni++)
            #pragma unroll
            for (int j = 0; j < 4; j++) acc[mi][ni][j] = 0.f;

    int nk = K >> 6;

    // ---- lane-constant ldmatrix base offsets (s=0); s-step is XOR (s<<5) ----
    // Valid because base bits [6:5] are zero (a_cb/b_cb is 0 or 16) so +s*32
    // never carries, and the SW128 mask depends only on bits [9:7] (row).
    int lq = lid >> 3, lr = lid & 7;
    uint32_t a_row = (uint32_t)(warp_m * 32 + ((lq & 1) << 3) + lr);
    uint32_t a_cb  = (uint32_t)((lq >> 1) << 4);
    uint32_t b_row = (uint32_t)(warp_n * 64 + ((lq >> 1) << 3) + lr);
    uint32_t b_cb  = (uint32_t)((lq & 1) << 4);
    uint32_t aoff0[2], boff0[4];
    #pragma unroll
    for (int mi = 0; mi < 2; mi++)
        aoff0[mi] = sw128((a_row + mi * 16) * ROWB + a_cb);
    #pragma unroll
    for (int p = 0; p < 4; p++)
        boff0[p] = sw128((b_row + p * 16) * ROWB + b_cb);

    // ---- loader: 3 tiles x 1024 16B-slots; 256 threads x 4 slots per tile ----
    int c8  = tid & 7;                 // 16B column within 128B row
    int r32 = tid >> 3;                // rows 0..31, stepped by +32
    uint32_t dofs[4];
    #pragma unroll
    for (int i = 0; i < 4; i++)
        dofs[i] = sw128((uint32_t)((r32 + 32 * i) * ROWB + c8 * 16));

    auto load_chunk = [&](int kc, int stage_sel){
        uint32_t stg = (uint32_t)stage_sel * (uint32_t)STG;
        const __half* sA = Ah + kc * 64;
        const __half* sH = Bh + kc * 64;
        const __half* sL = Bl + kc * 64;
        uint32_t baseA = sb + stg;
        uint32_t baseH = sb + stg + (uint32_t)TILEB;
        uint32_t baseL = sb + stg + 2u * (uint32_t)TILEB;
        #pragma unroll
        for (int i = 0; i < 4; i++){
            int row = r32 + 32 * i;
            cp16(baseA + dofs[i], sA + (size_t)row * lda + c8 * 8);
            cp16(baseH + dofs[i], sH + (size_t)row * K   + c8 * 8);
            cp16(baseL + dofs[i], sL + (size_t)row * K   + c8 * 8);
        }
        CP_COMMIT();
    };

    load_chunk(0, 0);

    for (int kc = 0; kc < nk; kc++){
        asm volatile("cp.async.wait_group 0;" ::: "memory");
        __syncthreads();   // loads of kc visible; all warps done reading the other stage
        if (kc + 1 < nk)
            load_chunk(kc + 1, (kc + 1) & 1);   // overlaps with compute of kc

        uint32_t stg_b = sb + (uint32_t)(kc & 1) * STG;
        uint32_t sAh = stg_b;
        uint32_t sBh = stg_b + TILEB;
        uint32_t sBl = stg_b + 2 * TILEB;

        #pragma unroll
        for (int s = 0; s < 4; s++){
            uint32_t sx = (uint32_t)(s << 5);
            uint32_t ah[2][4];
            #pragma unroll
            for (int mi = 0; mi < 2; mi++)
                LDSM_X4(ah[mi][0], ah[mi][1], ah[mi][2], ah[mi][3], sAh + (aoff0[mi] ^ sx));
            #pragma unroll
            for (int p = 0; p < 4; p++){
                uint32_t bh0, bh1, bh2, bh3, bl0, bl1, bl2, bl3;
                LDSM_X4(bh0, bh1, bh2, bh3, sBh + (boff0[p] ^ sx));
                LDSM_X4(bl0, bl1, bl2, bl3, sBl + (boff0[p] ^ sx));
                #pragma unroll
                for (int mi = 0; mi < 2; mi++){
                    MMA16816(acc[mi][2*p],   ah[mi], bh0, bh1);
                    MMA16816(acc[mi][2*p],   ah[mi], bl0, bl1);
                    MMA16816(acc[mi][2*p+1], ah[mi], bh2, bh3);
                    MMA16816(acc[mi][2*p+1], ah[mi], bl2, bl3);
                }
            }
        }
    }

    // ---------------- epilogue ----------------
    const float* biasp = bias + (size_t)t * Ntot;
    const __half* axh = nullptr; const __half* axl = nullptr;
    if (epi){
        axh = get_hbuf(aux_id, 0) + (size_t)t * BB * Ntot;
        axl = get_hbuf(aux_id, 1) + (size_t)t * BB * Ntot;
    }
    __half* oh = get_hbuf(out_id, 0) + (size_t)t * BB * Ntot;
    __half* ol = get_hbuf(out_id, 1) + (size_t)t * BB * Ntot;

    int g = lid >> 2, tig = lid & 3;
    #pragma unroll
    for (int mi = 0; mi < 2; mi++){
        #pragma unroll
        for (int ni = 0; ni < 8; ni++){
            int col = n0 + warp_n * 64 + ni * 8 + 2 * tig;
            float2 bv = *(const float2*)(biasp + col);
            int row0 = m0 + warp_m * 32 + mi * 16 + g;
            #pragma unroll
            for (int h = 0; h < 2; h++){
                int row = row0 + h * 8;
                size_t off = (size_t)row * Ntot + col;
                float v0 = acc[mi][ni][2*h]   + bv.x;
                float v1 = acc[mi][ni][2*h+1] + bv.y;
                float a0 = 0.f, a1 = 0.f;
                if (epi){
                    __half2 hv = *(const __half2*)(axh + off);
                    __half2 lv = *(const __half2*)(axl + off);
                    a0 = __half2float(hv.x) + __half2float(lv.x);
                    a1 = __half2float(hv.y) + __half2float(lv.y);
                }
                float r0, r1;
                if (epi == 0){
                    r0 = fmaxf(v0, 0.f); r1 = fmaxf(v1, 0.f);
                } else if (epi == 1){
                    r0 = a0 * (1.f / (1.f + __expf(-2.f * v0)));
                    r1 = a1 * (1.f / (1.f + __expf(-2.f * v1)));
                } else {
                    r0 = fmaxf(v0 * a0, 0.f); r1 = fmaxf(v1 * a1, 0.f);
                }
                __half h0v, l0v, h1v, l1v;
                split_f32(r0, h0v, l0v); split_f32(r1, h1v, l1v);
                *(__half2*)(oh + off) = __halves2half2(h0v, h1v);
                if (wlo)
                    *(__half2*)(ol + off) = __halves2half2(l0v, l1v);
            }
        }
    }
}

// ------------------------- output layer -----------------------------------
__global__ void out_k(const float* __restrict__ W2, const float* __restrict__ b2,
                      float* __restrict__ out){
    int b = blockIdx.x;
    int wid = threadIdx.x >> 5, lid = threadIdx.x & 31;   // wid = task
    const __half* xh = get_hbuf(HP_X1, 0) + ((size_t)wid * BB + b) * H1;
    const __half* xl = get_hbuf(HP_X1, 1) + ((size_t)wid * BB + b) * H1;
    const float* wr = W2 + (size_t)wid * H1;
    float s = 0.f;
    #pragma unroll
    for (int j = 0; j < 8; j++){
        int i = lid + 32 * j;
        s += (__half2float(xh[i]) + __half2float(xl[i])) * wr[i];
    }
    #pragma unroll
    for (int o = 16; o > 0; o >>= 1)
        s += __shfl_down_sync(0xFFFFFFFFu, s, o);
    if (lid == 0) out[(size_t)b * TT + wid] = s + b2[wid];
}

// ------------------------- launch -----------------------------------------
extern "C" void kernel_launch(void* const* d_in, const int* in_sizes, int n_in,
                              void* d_out, int out_size) {
    const float* prior    = (const float*)d_in[0];
    const float* gen      = (const float*)d_in[1];
    const float* pers     = (const float*)d_in[2];
    const float* tower_W0 = (const float*)d_in[3];
    const float* tower_b0 = (const float*)d_in[4];
    const float* tower_W1 = (const float*)d_in[5];
    const float* tower_b1 = (const float*)d_in[6];
    const float* tower_W2 = (const float*)d_in[7];
    const float* tower_b2 = (const float*)d_in[8];
    const float* ppn0_W   = (const float*)d_in[9];
    const float* ppn0_b   = (const float*)d_in[10];
    const float* gate0_W  = (const float*)d_in[11];
    const float* gate0_b  = (const float*)d_in[12];
    const float* ppn1_W   = (const float*)d_in[13];
    const float* ppn1_b   = (const float*)d_in[14];
    const float* gate1_W  = (const float*)d_in[15];
    const float* gate1_b  = (const float*)d_in[16];

    cudaFuncSetAttribute(gemm_fp16s,
                         cudaFuncAttributeMaxDynamicSharedMemorySize, SMEM_DYN);

    // launches 0,1,2: prep — launch index 5 (ncu -s 5 -c 1) is tower0 GEMM
    concat_convert_k<<<(BB * CCH) / 256, 256>>>(prior, gen);
    pers_convert_k<<<(BB * GGD) / 256, 256>>>(pers);
    transpose_all_k<<<dim3(1280, 1, TT), dim3(32, 8)>>>(
        ppn0_W, gate0_W, tower_W0, ppn1_W, gate1_W, tower_W1);

    // ppn0: h0 = relu(comb @ W + b)                 [K=768, N=512]
    gemm_fp16s<<<dim3(BB/128, H0/128, TT), 256, SMEM_DYN>>>(
        HP_COMB, 0, CCH, CCH, HP_WPPN0, ppn0_b, 0, HP_H0, H0, 0, 1);
    // gate0: g0 = h0 * sigmoid(2*(h0 @ Wg + b))     [K=512, N=512]
    gemm_fp16s<<<dim3(BB/128, H0/128, TT), 256, SMEM_DYN>>>(
        HP_H0, (size_t)BB*H0, H0, H0, HP_WGT0, gate0_b, HP_H0, HP_G0, H0, 1, 1);
    // tower0: x0 = relu((pers @ W0 + b0) * g0)      [K=512, N=512]   (profiled; x0 lo dead)
    gemm_fp16s<<<dim3(BB/128, H0/128, TT), 256, SMEM_DYN>>>(
        HP_PERS, 0, GGD, GGD, HP_WTW0, tower_b0, HP_G0, HP_X0, H0, 2, 0);
    // ppn1: h1 = relu(comb @ W + b)                 [K=768, N=256]
    gemm_fp16s<<<dim3(BB/128, H1/128, TT), 256, SMEM_DYN>>>(
        HP_COMB, 0, CCH, CCH, HP_WPPN1, ppn1_b, 0, HP_H1, H1, 0, 1);
    // gate1: g1 = h1 * sigmoid(2*(h1 @ Wg + b))     [K=256, N=256]
    gemm_fp16s<<<dim3(BB/128, H1/128, TT), 256, SMEM_DYN>>>(
        HP_H1, (size_t)BB*H1, H1, H1, HP_WGT1, gate1_b, HP_H1, HP_G1, H1, 1, 1);
    // tower1: x1 = relu((x0 @ W1 + b1) * g1)        [K=512, N=256]   (exact: x0 is fp16)
    gemm_fp16s<<<dim3(BB/128, H1/128, TT), 256, SMEM_DYN>>>(
        HP_X0, (size_t)BB*H0, H0, H0, HP_WTW1, tower_b1, HP_G1, HP_X1, H1, 2, 1);

    out_k<<<BB, 256>>>(tower_W2, tower_b2, (float*)d_out);
}